// round 15
// baseline (speedup 1.0000x reference)
#include <cuda_runtime.h>
#include <cuda_bf16.h>
#include <cuda_fp16.h>

typedef unsigned int u32;
typedef unsigned long long u64;
typedef unsigned short u16;

#define DN 128
#define NN 20000
#define EE 640000
#define ET 64                   // edges per CTA
#define NCTA (EE / ET)          // 10000
#define ASTR 528                // h1 row stride bytes (256 halves + pad)
#define YSTR 272                // x row stride bytes (136 halves)

// ---------------- device globals (no runtime alloc) ----------------
__device__ float g_x[NN * DN];
__device__ u32 g_xh[NN * 64];      // x as fp16 pairs (scatter source)
__device__ float g_out[NN * DN];
__device__ u32 g_yah[NN * 128];    // (x@W1a^T + b1) as fp16 pairs
__device__ u32 g_ybh[NN * 128];    // (x@W1b^T) as fp16 pairs
__device__ int g_e64;
// pre-packed B fragments in per-lane mma order
__device__ uint4 g_fh1[8192];   // W1 fp16 single: [og4][side2][ks8][nq4][lane32]
__device__ uint4 g_fh2[4096];   // W2 fp16 single: [og4][ks16][nq2][lane32]
__device__ uint4 g_fl[4096];    // lin_w bf16 hi/lo: [og8][ks8][lane32][hi/lo]
__device__ uint4 g_fn1[4096];   // nm_w1 bf16 hi/lo
__device__ uint4 g_fn2[4096];   // nm_w2 bf16 hi/lo

// ---------------- k_edge smem layout (bytes) ----------------
#define SB_ROWS 0
#define SB_COLS 256
#define SB_DE   512
#define SB_EMS  768
#define SB_ATT  1024
#define SB_PART 1280
#define SB_B2   2304
#define SB_W3   2816
#define SB_W1C  3328
#define SB_A    4352            // 64 x 528 = 33792 (fp16 h1 tile)
#define SB_XC   38144           // 64 x 256 = 16384 (fp16 x_col stage)
#define SMEM_EDGE 54528

// ---------------- k_xy smem layout ----------------
#define SY_A_HI 0               // 32 x 272 = 8704
#define SY_A_LO 8704
#define SY_B1   17408           // 256 f
#define SY_LB   18432           // 128 f
#define SMEM_Y  18944

// ---------------- k_node smem layout ----------------
#define SN_A_HI 0               // 32 x 272 = 8704
#define SN_A_LO 8704
#define SN_MID  17408           // 32 x 132 f = 16896
#define SN_B1   34304           // 128 f
#define SN_B2   34816
#define SN_G1   35328
#define SN_BB1  35840
#define SN_G2   36352
#define SN_BB2  36864
#define SMEM_N  37376

__device__ __forceinline__ u32 smem_u32(const void* p) {
    u32 a;
    asm("{ .reg .u64 t; cvta.to.shared.u64 t, %1; cvt.u32.u64 %0, t; }" : "=r"(a) : "l"(p));
    return a;
}
// accurate sigmoid (output path)
__device__ __forceinline__ float sigm(float v) {
    return __fdividef(1.0f, 1.0f + __expf(-v));
}
__device__ __forceinline__ float silu_(float v) { return v * sigm(v); }
// fast fp32 sigmoid (attenuated scalar paths)
__device__ __forceinline__ float tanhap(float x) {
    float r; asm("tanh.approx.f32 %0, %1;" : "=f"(r) : "f"(x)); return r;
}
__device__ __forceinline__ float sigm_f(float v) { return fmaf(tanhap(v * 0.5f), 0.5f, 0.5f); }
__device__ __forceinline__ float silu_f(float v) { return v * sigm_f(v); }

// half2 helpers (attenuated h1 path)
__device__ __forceinline__ u32 hadd2_(u32 a, u32 b) {
    u32 r; asm("add.rn.f16x2 %0, %1, %2;" : "=r"(r) : "r"(a), "r"(b)); return r;
}
__device__ __forceinline__ u32 hfma2_(u32 a, u32 b, u32 c) {
    u32 r; asm("fma.rn.f16x2 %0, %1, %2, %3;" : "=r"(r) : "r"(a), "r"(b), "r"(c)); return r;
}
__device__ __forceinline__ u32 silu_h2(u32 v) {
    const u32 h05 = 0x38003800u;   // half2(0.5, 0.5)
    u32 t, s;
    asm("mul.rn.f16x2 %0, %1, %2;" : "=r"(t) : "r"(v), "r"(h05));
    asm("tanh.approx.f16x2 %0, %1;" : "=r"(t) : "r"(t));
    asm("fma.rn.f16x2 %0, %1, %2, %3;" : "=r"(s) : "r"(t), "r"(h05), "r"(h05));
    asm("mul.rn.f16x2 %0, %1, %2;" : "=r"(s) : "r"(s), "r"(v));
    return s;
}

__device__ __forceinline__ void bsplit(float v, u16& h, u16& l) {
    __nv_bfloat16 hb = __float2bfloat16(v);
    __nv_bfloat16 lb = __float2bfloat16(v - __bfloat162float(hb));
    h = __bfloat16_as_ushort(hb);
    l = __bfloat16_as_ushort(lb);
}
__device__ __forceinline__ void bsplit2(float v0, float v1, u32& hp, u32& lp) {
    asm("cvt.rn.bf16x2.f32 %0, %1, %2;" : "=r"(hp) : "f"(v1), "f"(v0));
    float h0 = __uint_as_float(hp << 16);
    float h1 = __uint_as_float(hp & 0xffff0000u);
    asm("cvt.rn.bf16x2.f32 %0, %1, %2;" : "=r"(lp) : "f"(v1 - h1), "f"(v0 - h0));
}
__device__ __forceinline__ u32 hpack2(float v0, float v1) {
    u32 r;
    asm("cvt.rn.f16x2.f32 %0, %1, %2;" : "=r"(r) : "f"(v1), "f"(v0));
    return r;
}
__device__ __forceinline__ float2 hunpack2(u32 p) {
    return __half22float2(*(const __half2*)&p);
}

// ldmatrix m16k16 (A, row-major, stride S bytes)
template <int S>
__device__ __forceinline__ void ldmA(u32 r[4], u32 base, int row0, int kh) {
    int lane = threadIdx.x & 31;
    int quad = lane >> 3;
    u32 addr = base + (u32)(row0 + (lane & 7) + (quad & 1) * 8) * S +
               (u32)kh * 2 + (u32)(quad >> 1) * 16;
    asm volatile("ldmatrix.sync.aligned.m8n8.x4.shared.b16 {%0,%1,%2,%3}, [%4];"
                 : "=r"(r[0]), "=r"(r[1]), "=r"(r[2]), "=r"(r[3]) : "r"(addr));
}
__device__ __forceinline__ void mma16816(float d[4], const u32 a[4], u32 b0, u32 b1) {
    asm volatile("mma.sync.aligned.m16n8k16.row.col.f32.bf16.bf16.f32 "
                 "{%0,%1,%2,%3}, {%4,%5,%6,%7}, {%8,%9}, {%0,%1,%2,%3};"
                 : "+f"(d[0]), "+f"(d[1]), "+f"(d[2]), "+f"(d[3])
                 : "r"(a[0]), "r"(a[1]), "r"(a[2]), "r"(a[3]), "r"(b0), "r"(b1));
}
__device__ __forceinline__ void mmaf16(float d[4], const u32 a[4], u32 b0, u32 b1) {
    asm volatile("mma.sync.aligned.m16n8k16.row.col.f32.f16.f16.f32 "
                 "{%0,%1,%2,%3}, {%4,%5,%6,%7}, {%8,%9}, {%0,%1,%2,%3};"
                 : "+f"(d[0]), "+f"(d[1]), "+f"(d[2]), "+f"(d[3])
                 : "r"(a[0]), "r"(a[1]), "r"(a[2]), "r"(a[3]), "r"(b0), "r"(b1));
}

// pack a 128x128 K-major fp32 weight into bf16 hi/lo frag pairs
__device__ __forceinline__ void pack128(const float* __restrict__ w, uint4* tab, int j) {
    int lane = j & 31, ks = (j >> 5) & 7, og = (j >> 8) & 7;
    int nb0 = og * 16 + (lane >> 2);
    int kb = ks * 16 + (lane & 3) * 2;
    u32 wh[4], wl[4];
#pragma unroll
    for (int nb = 0; nb < 2; nb++)
#pragma unroll
        for (int r = 0; r < 2; r++) {
            const float* p = &w[(nb0 + nb * 8) * 128 + kb + r * 8];
            u16 h0, l0, h1, l1;
            bsplit(p[0], h0, l0);
            bsplit(p[1], h1, l1);
            wh[nb * 2 + r] = (u32)h0 | ((u32)h1 << 16);
            wl[nb * 2 + r] = (u32)l0 | ((u32)l1 << 16);
        }
    tab[j * 2] = make_uint4(wh[0], wh[1], wh[2], wh[3]);
    tab[j * 2 + 1] = make_uint4(wl[0], wl[1], wl[2], wl[3]);
}

// ---------------------------------------------------------------------------
// k_prep: pack weight fragment tables. grid 72 x 256.
// ---------------------------------------------------------------------------
__global__ void k_prep(const float* __restrict__ w1, const float* __restrict__ w2,
                       const float* __restrict__ lw, const float* __restrict__ nw1,
                       const float* __restrict__ nw2, const void* __restrict__ edges) {
    int idx = blockIdx.x * 256 + threadIdx.x;
    if (idx < 8192) {       // W1 fp16 single frags [256 out][257 k]
        int lane = idx & 31, nq = (idx >> 5) & 3, ks = (idx >> 7) & 7;
        int side = (idx >> 10) & 1, og = (idx >> 11) & 3;
        int nb0 = og * 64 + nq * 16 + (lane >> 2);
        int kb = side * 128 + ks * 16 + (lane & 3) * 2;
        u32 wf[4];
#pragma unroll
        for (int nb = 0; nb < 2; nb++)
#pragma unroll
            for (int r = 0; r < 2; r++) {
                const float* p = &w1[(nb0 + nb * 8) * 257 + kb + r * 8];
                wf[nb * 2 + r] = hpack2(p[0], p[1]);
            }
        g_fh1[idx] = make_uint4(wf[0], wf[1], wf[2], wf[3]);
    } else if (idx < 12288) {  // W2 fp16 single frags [128 out][256 k]
        int j = idx - 8192;
        int lane = j & 31, nq = (j >> 5) & 1, ks = (j >> 6) & 15, og = (j >> 10) & 3;
        int nb0 = og * 32 + nq * 16 + (lane >> 2);
        int kb = ks * 16 + (lane & 3) * 2;
        u32 wf[4];
#pragma unroll
        for (int nb = 0; nb < 2; nb++)
#pragma unroll
            for (int r = 0; r < 2; r++) {
                const float* p = &w2[(nb0 + nb * 8) * 256 + kb + r * 8];
                wf[nb * 2 + r] = hpack2(p[0], p[1]);
            }
        g_fh2[j] = make_uint4(wf[0], wf[1], wf[2], wf[3]);
    } else if (idx < 14336) {  // lin_w frags
        pack128(lw, g_fl, idx - 12288);
    } else if (idx < 16384) {  // nm_w1 frags
        pack128(nw1, g_fn1, idx - 14336);
    } else {                   // nm_w2 frags
        pack128(nw2, g_fn2, idx - 16384);
    }
    if (idx == 0) {
        const int* e32 = (const int*)edges;
        int nz = 0;
        for (int i = 0; i < 16; i++) nz |= e32[2 * i + 1];
        g_e64 = (nz == 0) ? 1 : 0;
    }
}

// ---------------------------------------------------------------------------
// k_xy: zero g_out rows; phase1 x = h@lin_w^T + lin_b (bf16 split) -> g_x,
//       g_xh; phase2 ya/yb = x@W1^T (single fp16).  32 nodes/CTA, 2 CTAs/SM.
// ---------------------------------------------------------------------------
__global__ __launch_bounds__(256, 2) void k_xy(const float* __restrict__ h,
                                               const float* __restrict__ lb,
                                               const float* __restrict__ b1) {
    extern __shared__ char smc[];
    u32 smb = smem_u32(smc);
    float* b1s = (float*)(smc + SY_B1);
    float* lbs = (float*)(smc + SY_LB);
    int tid = threadIdx.x, lane = tid & 31, warp = tid >> 5;
    int n0 = blockIdx.x * 32;

    // zero this CTA's g_out rows (replaces k_zero)
#pragma unroll
    for (int i = 0; i < 4; i++) {
        int idx = tid + i * 256;
        *(float4*)&g_out[(size_t)n0 * DN + idx * 4] = make_float4(0.f, 0.f, 0.f, 0.f);
    }

    b1s[tid] = b1[tid];
    if (tid < 128) lbs[tid] = lb[tid];
#pragma unroll
    for (int i = 0; i < 4; i++) {
        int el = warp * 4 + i;
        const float4 v = *(const float4*)&h[(size_t)(n0 + el) * DN + lane * 4];
        u32 hp0, lp0, hp1, lp1;
        bsplit2(v.x, v.y, hp0, lp0);
        bsplit2(v.z, v.w, hp1, lp1);
        *(u64*)(smc + SY_A_HI + el * YSTR + lane * 8) = (u64)hp0 | ((u64)hp1 << 32);
        *(u64*)(smc + SY_A_LO + el * YSTR + lane * 8) = (u64)lp0 | ((u64)lp1 << 32);
    }
    __syncthreads();

    // ---- phase 1: x = h@lin_w^T + lin_b (bf16 hi/lo split) ----
    {
        float accl[2][2][4] = {};
#pragma unroll
        for (int ks = 0; ks < 8; ks++) {
            int ka = ks * 16;
            u32 ah[2][4], al_[2][4];
            ldmA<YSTR>(ah[0], smb + SY_A_HI, 0, ka);
            ldmA<YSTR>(ah[1], smb + SY_A_HI, 16, ka);
            ldmA<YSTR>(al_[0], smb + SY_A_LO, 0, ka);
            ldmA<YSTR>(al_[1], smb + SY_A_LO, 16, ka);
            int fbase = ((warp * 8 + ks) * 32 + lane) * 2;
            uint4 fh = g_fl[fbase];
            uint4 fl = g_fl[fbase + 1];
#pragma unroll
            for (int mt = 0; mt < 2; mt++) {
                mma16816(accl[mt][0], ah[mt], fh.x, fh.y);
                mma16816(accl[mt][0], ah[mt], fl.x, fl.y);
                mma16816(accl[mt][0], al_[mt], fh.x, fh.y);
                mma16816(accl[mt][1], ah[mt], fh.z, fh.w);
                mma16816(accl[mt][1], ah[mt], fl.z, fl.w);
                mma16816(accl[mt][1], al_[mt], fh.z, fh.w);
            }
        }
        __syncthreads();   // done reading h tile; overlay fp16 x tile
        int r0 = lane >> 2, cb = (lane & 3) * 2;
#pragma unroll
        for (int mt = 0; mt < 2; mt++) {
#pragma unroll
            for (int nb = 0; nb < 2; nb++) {
                int o = warp * 16 + nb * 8 + cb;
                float ba = lbs[o], bb = lbs[o + 1];
                float v0 = accl[mt][nb][0] + ba, v1 = accl[mt][nb][1] + bb;
                float v2 = accl[mt][nb][2] + ba, v3 = accl[mt][nb][3] + bb;
                int nl = mt * 16 + r0;
                *(float2*)&g_x[(size_t)(n0 + nl) * DN + o] = make_float2(v0, v1);
                *(float2*)&g_x[(size_t)(n0 + nl + 8) * DN + o] = make_float2(v2, v3);
                u32 hp01 = hpack2(v0, v1);
                u32 hp23 = hpack2(v2, v3);
                g_xh[(size_t)(n0 + nl) * 64 + (o >> 1)] = hp01;
                g_xh[(size_t)(n0 + nl + 8) * 64 + (o >> 1)] = hp23;
                *(u32*)(smc + SY_A_HI + nl * YSTR + o * 2) = hp01;
                *(u32*)(smc + SY_A_HI + (nl + 8) * YSTR + o * 2) = hp23;
            }
        }
    }
    __syncthreads();

    // ---- phase 2: ya/yb single fp16 mma ----
    int side = warp >> 2, og1 = warp & 3;
    int r0 = lane >> 2, cb = (lane & 3) * 2;
    u32* dsth = side == 0 ? g_yah : g_ybh;
    float acc[2][8][4] = {};
#pragma unroll
    for (int ks = 0; ks < 8; ks++) {
        int ka = ks * 16;
        u32 ah[2][4];
        ldmA<YSTR>(ah[0], smb + SY_A_HI, 0, ka);
        ldmA<YSTR>(ah[1], smb + SY_A_HI, 16, ka);
        int fbase = (((og1 * 2 + side) * 8 + ks) * 4) * 32 + lane;
#pragma unroll
        for (int nq = 0; nq < 4; nq++) {
            uint4 f = g_fh1[fbase + nq * 32];
#pragma unroll
            for (int mt = 0; mt < 2; mt++) {
                mmaf16(acc[mt][nq * 2], ah[mt], f.x, f.y);
                mmaf16(acc[mt][nq * 2 + 1], ah[mt], f.z, f.w);
            }
        }
    }
#pragma unroll
    for (int mt = 0; mt < 2; mt++) {
        int node = n0 + mt * 16 + r0;
#pragma unroll
        for (int nb = 0; nb < 8; nb++) {
            int o = og1 * 64 + nb * 8 + cb;
            float ba = side == 0 ? b1s[o] : 0.0f;
            float bb = side == 0 ? b1s[o + 1] : 0.0f;
            dsth[(size_t)node * 128 + (o >> 1)] =
                hpack2(acc[mt][nb][0] + ba, acc[mt][nb][1] + bb);
            dsth[(size_t)(node + 8) * 128 + (o >> 1)] =
                hpack2(acc[mt][nb][2] + ba, acc[mt][nb][3] + bb);
        }
    }
}

// ---------------------------------------------------------------------------
// Fused edge kernel: half2 gather+silu (+x_col prefetch) -> GEMM2 (fp16 mma)
// -> att -> scatter from smem (red.global.v4).  64 edges/CTA, 4 CTAs/SM.
// ---------------------------------------------------------------------------
__global__ __launch_bounds__(256, 4) void k_edge(
    const float* __restrict__ dist, const float* __restrict__ emask,
    const float* __restrict__ w1, const float* __restrict__ b2,
    const float* __restrict__ w3, const float* __restrict__ b3,
    const void* __restrict__ edges) {
    extern __shared__ char smc[];
    u32 smb = smem_u32(smc);
    float* smf = (float*)smc;
    int* rows = (int*)(smc + SB_ROWS);
    int* cols = (int*)(smc + SB_COLS);

    int tid = threadIdx.x, lane = tid & 31, warp = tid >> 5;
    int eg = warp & 1, og = warp >> 1;
    int Eb = eg * 32;
    int e0 = blockIdx.x * ET;

    smf[SB_W1C / 4 + tid] = w1[tid * 257 + 256];
    if (tid < 128) {
        smf[SB_B2 / 4 + tid] = b2[tid];
        smf[SB_W3 / 4 + tid] = w3[tid];
    }
    if (tid < 64) {
        int e = e0 + tid;
        if (g_e64) {
            const long long* e64 = (const long long*)edges;
            rows[tid] = (int)e64[e];
            cols[tid] = (int)e64[EE + e];
        } else {
            const int* ei = (const int*)edges;
            rows[tid] = ei[e];
            cols[tid] = ei[EE + e];
        }
        float em = emask[e];
        smf[SB_EMS / 4 + tid] = em;
        smf[SB_DE / 4 + tid] = dist[e] * em;
    }
    __syncthreads();

    // ---- gather fp16 ya[row]+yb[col]+de*w1c -> silu; prefetch x_col ----
    {
        float4 wc0 = *(const float4*)(smf + SB_W1C / 4 + lane * 4);
        float4 wc1 = *(const float4*)(smf + SB_W1C / 4 + lane * 4 + 128);
        u32 wch[4];
        wch[0] = hpack2(wc0.x, wc0.y);
        wch[1] = hpack2(wc0.z, wc0.w);
        wch[2] = hpack2(wc1.x, wc1.y);
        wch[3] = hpack2(wc1.z, wc1.w);
#pragma unroll
        for (int i = 0; i < 8; i++) {
            int el = warp * 8 + i;
            int col = cols[el];
            const u32* ya = &g_yah[(size_t)rows[el] * 128];
            const u32* yb = &g_ybh[(size_t)col * 128];
            // prefetch fp16 x_col into smem for the scatter phase
            uint2 xc = *(const uint2*)&g_xh[(size_t)col * 64 + lane * 2];
            *(uint2*)(smc + SB_XC + el * 256 + lane * 8) = xc;
            u32 de2 = hpack2(smf[SB_DE / 4 + el], smf[SB_DE / 4 + el]);
#pragma unroll
            for (int j = 0; j < 2; j++) {
                int yo = lane * 2 + j * 64;
                uint2 pa = *(const uint2*)(ya + yo);
                uint2 pb = *(const uint2*)(yb + yo);
                u32 s0 = hfma2_(de2, wch[j * 2], hadd2_(pa.x, pb.x));
                u32 s1 = hfma2_(de2, wch[j * 2 + 1], hadd2_(pa.y, pb.y));
                s0 = silu_h2(s0);
                s1 = silu_h2(s1);
                *(u64*)(smc + SB_A + el * ASTR + (lane * 4 + j * 128) * 2) =
                    (u64)s0 | ((u64)s1 << 32);
            }
        }
    }
    __syncthreads();

    // ---- GEMM2 (fp16): D2[64e x 128o], warp slice 32e x 32o, K=256 ----
    float acc2[2][4][4] = {};
#pragma unroll
    for (int ks = 0; ks < 16; ks++) {
        int ka = ks * 16;
        u32 ah[2][4];
        ldmA<ASTR>(ah[0], smb + SB_A, Eb, ka);
        ldmA<ASTR>(ah[1], smb + SB_A, Eb + 16, ka);
        int fbase = ((og * 16 + ks) * 2) * 32 + lane;
#pragma unroll
        for (int nq = 0; nq < 2; nq++) {
            uint4 f = g_fh2[fbase + nq * 32];
#pragma unroll
            for (int mt = 0; mt < 2; mt++) {
                mmaf16(acc2[mt][nq * 2], ah[mt], f.x, f.y);
                mmaf16(acc2[mt][nq * 2 + 1], ah[mt], f.z, f.w);
            }
        }
    }

    // ---- epilogue2: att partials (silu_f), cross-og combine ----
    {
        int r0 = lane >> 2, cb = (lane & 3) * 2;
        float p[2][2] = {};
#pragma unroll
        for (int mt = 0; mt < 2; mt++)
#pragma unroll
            for (int nb = 0; nb < 4; nb++) {
                int o = og * 32 + nb * 8 + cb;
                float b2a = smf[SB_B2 / 4 + o], b2b = smf[SB_B2 / 4 + o + 1];
                float w3a = smf[SB_W3 / 4 + o], w3b = smf[SB_W3 / 4 + o + 1];
                p[mt][0] += silu_f(acc2[mt][nb][0] + b2a) * w3a + silu_f(acc2[mt][nb][1] + b2b) * w3b;
                p[mt][1] += silu_f(acc2[mt][nb][2] + b2a) * w3a + silu_f(acc2[mt][nb][3] + b2b) * w3b;
            }
#pragma unroll
        for (int off = 1; off <= 2; off <<= 1)
#pragma unroll
            for (int mt = 0; mt < 2; mt++) {
                p[mt][0] += __shfl_xor_sync(0xffffffffu, p[mt][0], off);
                p[mt][1] += __shfl_xor_sync(0xffffffffu, p[mt][1], off);
            }
        if ((lane & 3) == 0) {
#pragma unroll
            for (int mt = 0; mt < 2; mt++) {
                int e = Eb + mt * 16 + r0;
                smf[SB_PART / 4 + og * 64 + e] = p[mt][0];
                smf[SB_PART / 4 + og * 64 + e + 8] = p[mt][1];
            }
        }
    }
    __syncthreads();
    if (tid < 64) {
        float z = smf[SB_PART / 4 + tid] + smf[SB_PART / 4 + 64 + tid] +
                  smf[SB_PART / 4 + 128 + tid] + smf[SB_PART / 4 + 192 + tid] + b3[0];
        smf[SB_ATT / 4 + tid] = sigm(z) * smf[SB_EMS / 4 + tid];  // accurate sigmoid
    }
    __syncthreads();

    // ---- scatter from smem: g_out[row] += x_col * att ----
#pragma unroll
    for (int i = 0; i < 8; i++) {
        int el = warp * 8 + i;
        float a = smf[SB_ATT / 4 + el];
        uint2 xc = *(const uint2*)(smc + SB_XC + el * 256 + lane * 8);
        float2 v01 = hunpack2(xc.x), v23 = hunpack2(xc.y);
        float* dst = &g_out[(size_t)rows[el] * DN + lane * 4];
        asm volatile("red.global.add.v4.f32 [%0], {%1, %2, %3, %4};"
                     :: "l"(dst), "f"(v01.x * a), "f"(v01.y * a),
                        "f"(v23.x * a), "f"(v23.y * a)
                     : "memory");
    }
}

// ---------------------------------------------------------------------------
// k_node (mma, split-bf16 — output path): node_mlp + residual + LN + silu.
// ---------------------------------------------------------------------------
__global__ __launch_bounds__(256, 3) void k_node(
    const float* __restrict__ b1, const float* __restrict__ g1,
    const float* __restrict__ bb1, const float* __restrict__ b2,
    const float* __restrict__ g2, const float* __restrict__ bb2,
    float* __restrict__ out) {
    extern __shared__ char smc[];
    u32 smb = smem_u32(smc);
    float* mid = (float*)(smc + SN_MID);
    float* b1s = (float*)(smc + SN_B1);
    float* b2s = (float*)(smc + SN_B2);
    float* g1s = (float*)(smc + SN_G1);
    float* bb1s = (float*)(smc + SN_BB1);
    float* g2s = (float*)(smc + SN_G2);
    float* bb2s = (float*)(smc + SN_BB2);
    int tid = threadIdx.x, lane = tid & 31, warp = tid >> 5;
    int n0 = blockIdx.x * 32;

    if (tid < 128) {
        b1s[tid] = b1[tid]; b2s[tid] = b2[tid];
        g1s[tid] = g1[tid]; bb1s[tid] = bb1[tid];
        g2s[tid] = g2[tid]; bb2s[tid] = bb2[tid];
    }
#pragma unroll
    for (int i = 0; i < 4; i++) {
        int el = warp * 4 + i;
        float4 v = *(const float4*)&g_out[(size_t)(n0 + el) * DN + lane * 4];
        v.x *= 0.01f; v.y *= 0.01f; v.z *= 0.01f; v.w *= 0.01f;
        u32 hp0, lp0, hp1, lp1;
        bsplit2(v.x, v.y, hp0, lp0);
        bsplit2(v.z, v.w, hp1, lp1);
        *(u64*)(smc + SN_A_HI + el * YSTR + lane * 8) = (u64)hp0 | ((u64)hp1 << 32);
        *(u64*)(smc + SN_A_LO + el * YSTR + lane * 8) = (u64)lp0 | ((u64)lp1 << 32);
    }
    __syncthreads();

    int r0 = lane >> 2, cb = (lane & 3) * 2;

    // ---- GEMM1 (nm_w1) ----
    {
        float acc[2][2][4] = {};
#pragma unroll
        for (int ks = 0; ks < 8; ks++) {
            int ka = ks * 16;
            u32 ah[2][4], al_[2][4];
            ldmA<YSTR>(ah[0], smb + SN_A_HI, 0, ka);
            ldmA<YSTR>(ah[1], smb + SN_A_HI, 16, ka);
            ldmA<YSTR>(al_[0], smb + SN_A_LO, 0, ka);
            ldmA<YSTR>(al_[1], smb + SN_A_LO, 16, ka);
            int fbase = ((warp * 8 + ks) * 32 + lane) * 2;
            uint4 fh = g_fn1[fbase];
            uint4 fl = g_fn1[fbase + 1];
#pragma unroll
            for (int mt = 0; mt < 2; mt++) {
                mma16816(acc[mt][0], ah[mt], fh.x, fh.y);
                mma16816(acc[mt][0], ah[mt], fl.x, fl.y);
                mma16816(acc[mt][0], al_[mt], fh.x, fh.y);
                mma16816(acc[mt][1], ah[mt], fh.z, fh.w);
                mma16816(acc[mt][1], ah[mt], fl.z, fl.w);
                mma16816(acc[mt][1], al_[mt], fh.z, fh.w);
            }
        }
#pragma unroll
        for (int mt = 0; mt < 2; mt++)
#pragma unroll
            for (int nb = 0; nb < 2; nb++) {
                int o = warp * 16 + nb * 8 + cb;
                float ba = b1s[o], bb = b1s[o + 1];
                int nl = mt * 16 + r0;
                *(float2*)&mid[nl * 132 + o] = make_float2(acc[mt][nb][0] + ba, acc[mt][nb][1] + bb);
                *(float2*)&mid[(nl + 8) * 132 + o] = make_float2(acc[mt][nb][2] + ba, acc[mt][nb][3] + bb);
            }
    }
    __syncthreads();

    // ---- LN1 + silu_f -> A ----
#pragma unroll
    for (int i = 0; i < 4; i++) {
        int nl = warp * 4 + i;
        float v[4], s1 = 0.f, s2 = 0.f;
#pragma unroll
        for (int j = 0; j < 4; j++) {
            v[j] = mid[nl * 132 + lane + 32 * j];
            s1 += v[j]; s2 += v[j] * v[j];
        }
#pragma unroll
        for (int off = 16; off > 0; off >>= 1) {
            s1 += __shfl_xor_sync(0xffffffffu, s1, off);
            s2 += __shfl_xor_sync(0xffffffffu, s2, off);
        }
        float mean = s1 * (1.0f / 128.0f);
        float var = s2 * (1.0f / 128.0f) - mean * mean;
        float inv = rsqrtf(var + 1e-5f);
#pragma unroll
        for (int j = 0; j < 4; j++) {
            int o = lane + 32 * j;
            float y = silu_f((v[j] - mean) * inv * g1s[o] + bb1s[o]);
            u16 hh, ll;
            bsplit(y, hh, ll);
            *(u16*)(smc + SN_A_HI + nl * YSTR + o * 2) = hh;
            *(u16*)(smc + SN_A_LO + nl * YSTR + o * 2) = ll;
        }
    }
    __syncthreads();

    // ---- GEMM2 (nm_w2) ----
    {
        float acc[2][2][4] = {};
#pragma unroll
        for (int ks = 0; ks < 8; ks++) {
            int ka = ks * 16;
            u32 ah[2][4], al_[2][4];
            ldmA<YSTR>(ah[0], smb + SN_A_HI, 0, ka);
            ldmA<YSTR>(ah[1], smb + SN_A_HI, 16, ka);
            ldmA<YSTR>(al_[0], smb + SN_A_LO, 0, ka);
            ldmA<YSTR>(al_[1], smb + SN_A_LO, 16, ka);
            int fbase = ((warp * 8 + ks) * 32 + lane) * 2;
            uint4 fh = g_fn2[fbase];
            uint4 fl = g_fn2[fbase + 1];
#pragma unroll
            for (int mt = 0; mt < 2; mt++) {
                mma16816(acc[mt][0], ah[mt], fh.x, fh.y);
                mma16816(acc[mt][0], ah[mt], fl.x, fl.y);
                mma16816(acc[mt][0], al_[mt], fh.x, fh.y);
                mma16816(acc[mt][1], ah[mt], fh.z, fh.w);
                mma16816(acc[mt][1], ah[mt], fl.z, fl.w);
                mma16816(acc[mt][1], al_[mt], fh.z, fh.w);
            }
        }
#pragma unroll
        for (int mt = 0; mt < 2; mt++)
#pragma unroll
            for (int nb = 0; nb < 2; nb++) {
                int o = warp * 16 + nb * 8 + cb;
                float ba = b2s[o], bb = b2s[o + 1];
                int nl = mt * 16 + r0;
                *(float2*)&mid[nl * 132 + o] = make_float2(acc[mt][nb][0] + ba, acc[mt][nb][1] + bb);
                *(float2*)&mid[(nl + 8) * 132 + o] = make_float2(acc[mt][nb][2] + ba, acc[mt][nb][3] + bb);
            }
    }
    __syncthreads();

    // ---- + residual, LN2, silu (accurate), store ----
#pragma unroll
    for (int i = 0; i < 4; i++) {
        int nl = warp * 4 + i;
        float v[4], s1 = 0.f, s2 = 0.f;
#pragma unroll
        for (int j = 0; j < 4; j++) {
            int o = lane + 32 * j;
            v[j] = mid[nl * 132 + o] + g_x[(size_t)(n0 + nl) * DN + o];
            s1 += v[j]; s2 += v[j] * v[j];
        }
#pragma unroll
        for (int off = 16; off > 0; off >>= 1) {
            s1 += __shfl_xor_sync(0xffffffffu, s1, off);
            s2 += __shfl_xor_sync(0xffffffffu, s2, off);
        }
        float mean = s1 * (1.0f / 128.0f);
        float var = s2 * (1.0f / 128.0f) - mean * mean;
        float inv = rsqrtf(var + 1e-5f);
#pragma unroll
        for (int j = 0; j < 4; j++) {
            int o = lane + 32 * j;
            float y = (v[j] - mean) * inv * g2s[o] + bb2s[o];
            out[(size_t)(n0 + nl) * DN + o] = silu_(y);
        }
    }
}

// ---------------------------------------------------------------------------
extern "C" void kernel_launch(void* const* d_in, const int* in_sizes, int n_in,
                              void* d_out, int out_size) {
    const float* h = (const float*)d_in[0];
    const float* distances = (const float*)d_in[1];
    const float* edge_mask = (const float*)d_in[3];
    const float* lin_w = (const float*)d_in[4];
    const float* lin_b = (const float*)d_in[5];
    const float* att_w1 = (const float*)d_in[6];
    const float* att_b1 = (const float*)d_in[7];
    const float* att_w2 = (const float*)d_in[8];
    const float* att_b2 = (const float*)d_in[9];
    const float* att_w3 = (const float*)d_in[10];
    const float* att_b3 = (const float*)d_in[11];
    const float* nm_w1 = (const float*)d_in[12];
    const float* nm_b1 = (const float*)d_in[13];
    const float* nm_ln_g = (const float*)d_in[14];
    const float* nm_ln_b = (const float*)d_in[15];
    const float* nm_w2 = (const float*)d_in[16];
    const float* nm_b2 = (const float*)d_in[17];
    const float* ln_g = (const float*)d_in[18];
    const float* ln_b = (const float*)d_in[19];
    const void* edges = d_in[20];

    cudaFuncSetAttribute(k_xy, cudaFuncAttributeMaxDynamicSharedMemorySize, SMEM_Y);
    cudaFuncSetAttribute(k_edge, cudaFuncAttributeMaxDynamicSharedMemorySize, SMEM_EDGE);
    cudaFuncSetAttribute(k_node, cudaFuncAttributeMaxDynamicSharedMemorySize, SMEM_N);

    k_prep<<<72, 256>>>(att_w1, att_w2, lin_w, nm_w1, nm_w2, edges);
    k_xy<<<625, 256, SMEM_Y>>>(h, lin_b, att_b1);
    k_edge<<<NCTA, 256, SMEM_EDGE>>>(distances, edge_mask, att_w1, att_b2,
                                     att_w3, att_b3, edges);
    k_node<<<625, 256, SMEM_N>>>(nm_b1, nm_ln_g, nm_ln_b,
                                 nm_b2, ln_g, ln_b, (float*)d_out);
}

// round 16
// speedup vs baseline: 1.0250x; 1.0250x over previous
#include <cuda_runtime.h>
#include <cuda_bf16.h>
#include <cuda_fp16.h>

typedef unsigned int u32;
typedef unsigned long long u64;
typedef unsigned short u16;

#define DN 128
#define NN 20000
#define EE 640000
#define ET 64                   // edges per CTA
#define NCTA (EE / ET)          // 10000
#define ASTR 528                // h1 row stride bytes (256 halves + pad)
#define YSTR 272                // x row stride bytes (136 halves)

// ---------------- device globals (no runtime alloc) ----------------
__device__ float g_x[NN * DN];
__device__ float g_out[NN * DN];
__device__ u32 g_yah[NN * 128];    // (x@W1a^T + b1) as fp16 pairs
__device__ u32 g_ybh[NN * 128];    // (x@W1b^T) as fp16 pairs
__device__ int g_e64;
// pre-packed B fragments in per-lane mma order
__device__ uint4 g_fh1[8192];   // W1 fp16 single: [og4][side2][ks8][nq4][lane32]
__device__ uint4 g_fh2[4096];   // W2 fp16 single: [og4][ks16][nq2][lane32]
__device__ uint4 g_fl[4096];    // lin_w bf16 hi/lo: [og8][ks8][lane32][hi/lo]
__device__ uint4 g_fn1[4096];   // nm_w1 bf16 hi/lo
__device__ uint4 g_fn2[4096];   // nm_w2 bf16 hi/lo

// ---------------- k_edge smem layout (bytes) ----------------
#define SB_ROWS 0
#define SB_COLS 256
#define SB_DE   512
#define SB_EMS  768
#define SB_ATT  1024
#define SB_PART 1280
#define SB_B2   2304
#define SB_W3   2816
#define SB_W1C  3328
#define SB_A    4352            // 64 x 528 = 33792 (fp16 h1 tile)
#define SMEM_EDGE 38144

// ---------------- k_xy smem layout ----------------
#define SY_A_HI 0               // 32 x 272 = 8704
#define SY_A_LO 8704
#define SY_B1   17408           // 256 f
#define SY_LB   18432           // 128 f
#define SMEM_Y  18944

// ---------------- k_node smem layout ----------------
#define SN_A_HI 0               // 32 x 272 = 8704
#define SN_A_LO 8704
#define SN_MID  17408           // 32 x 132 f = 16896
#define SN_B1   34304           // 128 f
#define SN_B2   34816
#define SN_G1   35328
#define SN_BB1  35840
#define SN_G2   36352
#define SN_BB2  36864
#define SMEM_N  37376

__device__ __forceinline__ u32 smem_u32(const void* p) {
    u32 a;
    asm("{ .reg .u64 t; cvta.to.shared.u64 t, %1; cvt.u32.u64 %0, t; }" : "=r"(a) : "l"(p));
    return a;
}
// accurate sigmoid (output path)
__device__ __forceinline__ float sigm(float v) {
    return __fdividef(1.0f, 1.0f + __expf(-v));
}
__device__ __forceinline__ float silu_(float v) { return v * sigm(v); }
// fast fp32 sigmoid (attenuated scalar paths)
__device__ __forceinline__ float tanhap(float x) {
    float r; asm("tanh.approx.f32 %0, %1;" : "=f"(r) : "f"(x)); return r;
}
__device__ __forceinline__ float sigm_f(float v) { return fmaf(tanhap(v * 0.5f), 0.5f, 0.5f); }
__device__ __forceinline__ float silu_f(float v) { return v * sigm_f(v); }

// half2 helpers (attenuated h1 path)
__device__ __forceinline__ u32 hadd2_(u32 a, u32 b) {
    u32 r; asm("add.rn.f16x2 %0, %1, %2;" : "=r"(r) : "r"(a), "r"(b)); return r;
}
__device__ __forceinline__ u32 hfma2_(u32 a, u32 b, u32 c) {
    u32 r; asm("fma.rn.f16x2 %0, %1, %2, %3;" : "=r"(r) : "r"(a), "r"(b), "r"(c)); return r;
}
__device__ __forceinline__ u32 silu_h2(u32 v) {
    const u32 h05 = 0x38003800u;   // half2(0.5, 0.5)
    u32 t, s;
    asm("mul.rn.f16x2 %0, %1, %2;" : "=r"(t) : "r"(v), "r"(h05));
    asm("tanh.approx.f16x2 %0, %1;" : "=r"(t) : "r"(t));
    asm("fma.rn.f16x2 %0, %1, %2, %3;" : "=r"(s) : "r"(t), "r"(h05), "r"(h05));
    asm("mul.rn.f16x2 %0, %1, %2;" : "=r"(s) : "r"(s), "r"(v));
    return s;
}

__device__ __forceinline__ void bsplit(float v, u16& h, u16& l) {
    __nv_bfloat16 hb = __float2bfloat16(v);
    __nv_bfloat16 lb = __float2bfloat16(v - __bfloat162float(hb));
    h = __bfloat16_as_ushort(hb);
    l = __bfloat16_as_ushort(lb);
}
__device__ __forceinline__ void bsplit2(float v0, float v1, u32& hp, u32& lp) {
    asm("cvt.rn.bf16x2.f32 %0, %1, %2;" : "=r"(hp) : "f"(v1), "f"(v0));
    float h0 = __uint_as_float(hp << 16);
    float h1 = __uint_as_float(hp & 0xffff0000u);
    asm("cvt.rn.bf16x2.f32 %0, %1, %2;" : "=r"(lp) : "f"(v1 - h1), "f"(v0 - h0));
}
__device__ __forceinline__ u32 hpack2(float v0, float v1) {
    u32 r;
    asm("cvt.rn.f16x2.f32 %0, %1, %2;" : "=r"(r) : "f"(v1), "f"(v0));
    return r;
}
__device__ __forceinline__ float2 hunpack2(u32 p) {
    return __half22float2(*(const __half2*)&p);
}

// ldmatrix m16k16 (A, row-major, stride S bytes)
template <int S>
__device__ __forceinline__ void ldmA(u32 r[4], u32 base, int row0, int kh) {
    int lane = threadIdx.x & 31;
    int quad = lane >> 3;
    u32 addr = base + (u32)(row0 + (lane & 7) + (quad & 1) * 8) * S +
               (u32)kh * 2 + (u32)(quad >> 1) * 16;
    asm volatile("ldmatrix.sync.aligned.m8n8.x4.shared.b16 {%0,%1,%2,%3}, [%4];"
                 : "=r"(r[0]), "=r"(r[1]), "=r"(r[2]), "=r"(r[3]) : "r"(addr));
}
__device__ __forceinline__ void mma16816(float d[4], const u32 a[4], u32 b0, u32 b1) {
    asm volatile("mma.sync.aligned.m16n8k16.row.col.f32.bf16.bf16.f32 "
                 "{%0,%1,%2,%3}, {%4,%5,%6,%7}, {%8,%9}, {%0,%1,%2,%3};"
                 : "+f"(d[0]), "+f"(d[1]), "+f"(d[2]), "+f"(d[3])
                 : "r"(a[0]), "r"(a[1]), "r"(a[2]), "r"(a[3]), "r"(b0), "r"(b1));
}
__device__ __forceinline__ void mmaf16(float d[4], const u32 a[4], u32 b0, u32 b1) {
    asm volatile("mma.sync.aligned.m16n8k16.row.col.f32.f16.f16.f32 "
                 "{%0,%1,%2,%3}, {%4,%5,%6,%7}, {%8,%9}, {%0,%1,%2,%3};"
                 : "+f"(d[0]), "+f"(d[1]), "+f"(d[2]), "+f"(d[3])
                 : "r"(a[0]), "r"(a[1]), "r"(a[2]), "r"(a[3]), "r"(b0), "r"(b1));
}

// pack a 128x128 K-major fp32 weight into bf16 hi/lo frag pairs
__device__ __forceinline__ void pack128(const float* __restrict__ w, uint4* tab, int j) {
    int lane = j & 31, ks = (j >> 5) & 7, og = (j >> 8) & 7;
    int nb0 = og * 16 + (lane >> 2);
    int kb = ks * 16 + (lane & 3) * 2;
    u32 wh[4], wl[4];
#pragma unroll
    for (int nb = 0; nb < 2; nb++)
#pragma unroll
        for (int r = 0; r < 2; r++) {
            const float* p = &w[(nb0 + nb * 8) * 128 + kb + r * 8];
            u16 h0, l0, h1, l1;
            bsplit(p[0], h0, l0);
            bsplit(p[1], h1, l1);
            wh[nb * 2 + r] = (u32)h0 | ((u32)h1 << 16);
            wl[nb * 2 + r] = (u32)l0 | ((u32)l1 << 16);
        }
    tab[j * 2] = make_uint4(wh[0], wh[1], wh[2], wh[3]);
    tab[j * 2 + 1] = make_uint4(wl[0], wl[1], wl[2], wl[3]);
}

// ---------------------------------------------------------------------------
// k_prep: pack weight fragment tables. grid 72 x 256.
// ---------------------------------------------------------------------------
__global__ void k_prep(const float* __restrict__ w1, const float* __restrict__ w2,
                       const float* __restrict__ lw, const float* __restrict__ nw1,
                       const float* __restrict__ nw2, const void* __restrict__ edges) {
    int idx = blockIdx.x * 256 + threadIdx.x;
    if (idx < 8192) {       // W1 fp16 single frags [256 out][257 k]
        int lane = idx & 31, nq = (idx >> 5) & 3, ks = (idx >> 7) & 7;
        int side = (idx >> 10) & 1, og = (idx >> 11) & 3;
        int nb0 = og * 64 + nq * 16 + (lane >> 2);
        int kb = side * 128 + ks * 16 + (lane & 3) * 2;
        u32 wf[4];
#pragma unroll
        for (int nb = 0; nb < 2; nb++)
#pragma unroll
            for (int r = 0; r < 2; r++) {
                const float* p = &w1[(nb0 + nb * 8) * 257 + kb + r * 8];
                wf[nb * 2 + r] = hpack2(p[0], p[1]);
            }
        g_fh1[idx] = make_uint4(wf[0], wf[1], wf[2], wf[3]);
    } else if (idx < 12288) {  // W2 fp16 single frags [128 out][256 k]
        int j = idx - 8192;
        int lane = j & 31, nq = (j >> 5) & 1, ks = (j >> 6) & 15, og = (j >> 10) & 3;
        int nb0 = og * 32 + nq * 16 + (lane >> 2);
        int kb = ks * 16 + (lane & 3) * 2;
        u32 wf[4];
#pragma unroll
        for (int nb = 0; nb < 2; nb++)
#pragma unroll
            for (int r = 0; r < 2; r++) {
                const float* p = &w2[(nb0 + nb * 8) * 256 + kb + r * 8];
                wf[nb * 2 + r] = hpack2(p[0], p[1]);
            }
        g_fh2[j] = make_uint4(wf[0], wf[1], wf[2], wf[3]);
    } else if (idx < 14336) {  // lin_w frags
        pack128(lw, g_fl, idx - 12288);
    } else if (idx < 16384) {  // nm_w1 frags
        pack128(nw1, g_fn1, idx - 14336);
    } else {                   // nm_w2 frags
        pack128(nw2, g_fn2, idx - 16384);
    }
    if (idx == 0) {
        const int* e32 = (const int*)edges;
        int nz = 0;
        for (int i = 0; i < 16; i++) nz |= e32[2 * i + 1];
        g_e64 = (nz == 0) ? 1 : 0;
    }
}

// ---------------------------------------------------------------------------
// k_xy: zero g_out rows; phase1 x = h@lin_w^T + lin_b (bf16 split);
//       phase2 ya/yb = x@W1^T (single fp16).  32 nodes/CTA, 2 CTAs/SM.
// ---------------------------------------------------------------------------
__global__ __launch_bounds__(256, 2) void k_xy(const float* __restrict__ h,
                                               const float* __restrict__ lb,
                                               const float* __restrict__ b1) {
    extern __shared__ char smc[];
    u32 smb = smem_u32(smc);
    float* b1s = (float*)(smc + SY_B1);
    float* lbs = (float*)(smc + SY_LB);
    int tid = threadIdx.x, lane = tid & 31, warp = tid >> 5;
    int n0 = blockIdx.x * 32;

    // zero this CTA's g_out rows (replaces k_zero launch)
#pragma unroll
    for (int i = 0; i < 4; i++) {
        int idx = tid + i * 256;
        *(float4*)&g_out[(size_t)n0 * DN + idx * 4] = make_float4(0.f, 0.f, 0.f, 0.f);
    }

    b1s[tid] = b1[tid];
    if (tid < 128) lbs[tid] = lb[tid];
#pragma unroll
    for (int i = 0; i < 4; i++) {
        int el = warp * 4 + i;
        const float4 v = *(const float4*)&h[(size_t)(n0 + el) * DN + lane * 4];
        u32 hp0, lp0, hp1, lp1;
        bsplit2(v.x, v.y, hp0, lp0);
        bsplit2(v.z, v.w, hp1, lp1);
        *(u64*)(smc + SY_A_HI + el * YSTR + lane * 8) = (u64)hp0 | ((u64)hp1 << 32);
        *(u64*)(smc + SY_A_LO + el * YSTR + lane * 8) = (u64)lp0 | ((u64)lp1 << 32);
    }
    __syncthreads();

    // ---- phase 1: x = h@lin_w^T + lin_b (bf16 hi/lo split) ----
    {
        float accl[2][2][4] = {};
#pragma unroll
        for (int ks = 0; ks < 8; ks++) {
            int ka = ks * 16;
            u32 ah[2][4], al_[2][4];
            ldmA<YSTR>(ah[0], smb + SY_A_HI, 0, ka);
            ldmA<YSTR>(ah[1], smb + SY_A_HI, 16, ka);
            ldmA<YSTR>(al_[0], smb + SY_A_LO, 0, ka);
            ldmA<YSTR>(al_[1], smb + SY_A_LO, 16, ka);
            int fbase = ((warp * 8 + ks) * 32 + lane) * 2;
            uint4 fh = g_fl[fbase];
            uint4 fl = g_fl[fbase + 1];
#pragma unroll
            for (int mt = 0; mt < 2; mt++) {
                mma16816(accl[mt][0], ah[mt], fh.x, fh.y);
                mma16816(accl[mt][0], ah[mt], fl.x, fl.y);
                mma16816(accl[mt][0], al_[mt], fh.x, fh.y);
                mma16816(accl[mt][1], ah[mt], fh.z, fh.w);
                mma16816(accl[mt][1], ah[mt], fl.z, fl.w);
                mma16816(accl[mt][1], al_[mt], fh.z, fh.w);
            }
        }
        __syncthreads();   // done reading h tile; overlay fp16 x tile
        int r0 = lane >> 2, cb = (lane & 3) * 2;
#pragma unroll
        for (int mt = 0; mt < 2; mt++) {
#pragma unroll
            for (int nb = 0; nb < 2; nb++) {
                int o = warp * 16 + nb * 8 + cb;
                float ba = lbs[o], bb = lbs[o + 1];
                float v0 = accl[mt][nb][0] + ba, v1 = accl[mt][nb][1] + bb;
                float v2 = accl[mt][nb][2] + ba, v3 = accl[mt][nb][3] + bb;
                int nl = mt * 16 + r0;
                *(float2*)&g_x[(size_t)(n0 + nl) * DN + o] = make_float2(v0, v1);
                *(float2*)&g_x[(size_t)(n0 + nl + 8) * DN + o] = make_float2(v2, v3);
                *(u32*)(smc + SY_A_HI + nl * YSTR + o * 2) = hpack2(v0, v1);
                *(u32*)(smc + SY_A_HI + (nl + 8) * YSTR + o * 2) = hpack2(v2, v3);
            }
        }
    }
    __syncthreads();

    // ---- phase 2: ya/yb single fp16 mma ----
    int side = warp >> 2, og1 = warp & 3;
    int r0 = lane >> 2, cb = (lane & 3) * 2;
    u32* dsth = side == 0 ? g_yah : g_ybh;
    float acc[2][8][4] = {};
#pragma unroll
    for (int ks = 0; ks < 8; ks++) {
        int ka = ks * 16;
        u32 ah[2][4];
        ldmA<YSTR>(ah[0], smb + SY_A_HI, 0, ka);
        ldmA<YSTR>(ah[1], smb + SY_A_HI, 16, ka);
        int fbase = (((og1 * 2 + side) * 8 + ks) * 4) * 32 + lane;
#pragma unroll
        for (int nq = 0; nq < 4; nq++) {
            uint4 f = g_fh1[fbase + nq * 32];
#pragma unroll
            for (int mt = 0; mt < 2; mt++) {
                mmaf16(acc[mt][nq * 2], ah[mt], f.x, f.y);
                mmaf16(acc[mt][nq * 2 + 1], ah[mt], f.z, f.w);
            }
        }
    }
#pragma unroll
    for (int mt = 0; mt < 2; mt++) {
        int node = n0 + mt * 16 + r0;
#pragma unroll
        for (int nb = 0; nb < 8; nb++) {
            int o = og1 * 64 + nb * 8 + cb;
            float ba = side == 0 ? b1s[o] : 0.0f;
            float bb = side == 0 ? b1s[o + 1] : 0.0f;
            dsth[(size_t)node * 128 + (o >> 1)] =
                hpack2(acc[mt][nb][0] + ba, acc[mt][nb][1] + bb);
            dsth[(size_t)(node + 8) * 128 + (o >> 1)] =
                hpack2(acc[mt][nb][2] + ba, acc[mt][nb][3] + bb);
        }
    }
}

// ---------------------------------------------------------------------------
// Fused edge kernel (R14 config): half2 gather+silu -> GEMM2 (fp16 mma)
// -> att -> scatter fp32 x_col (red.global.v4).  64 edges/CTA, 4 CTAs/SM.
// ---------------------------------------------------------------------------
__global__ __launch_bounds__(256, 4) void k_edge(
    const float* __restrict__ dist, const float* __restrict__ emask,
    const float* __restrict__ w1, const float* __restrict__ b2,
    const float* __restrict__ w3, const float* __restrict__ b3,
    const void* __restrict__ edges) {
    extern __shared__ char smc[];
    u32 smb = smem_u32(smc);
    float* smf = (float*)smc;
    int* rows = (int*)(smc + SB_ROWS);
    int* cols = (int*)(smc + SB_COLS);

    int tid = threadIdx.x, lane = tid & 31, warp = tid >> 5;
    int eg = warp & 1, og = warp >> 1;
    int Eb = eg * 32;
    int e0 = blockIdx.x * ET;

    smf[SB_W1C / 4 + tid] = w1[tid * 257 + 256];
    if (tid < 128) {
        smf[SB_B2 / 4 + tid] = b2[tid];
        smf[SB_W3 / 4 + tid] = w3[tid];
    }
    if (tid < 64) {
        int e = e0 + tid;
        if (g_e64) {
            const long long* e64 = (const long long*)edges;
            rows[tid] = (int)e64[e];
            cols[tid] = (int)e64[EE + e];
        } else {
            const int* ei = (const int*)edges;
            rows[tid] = ei[e];
            cols[tid] = ei[EE + e];
        }
        float em = emask[e];
        smf[SB_EMS / 4 + tid] = em;
        smf[SB_DE / 4 + tid] = dist[e] * em;
    }
    __syncthreads();

    // ---- gather fp16 ya[row]+yb[col]+de*w1c -> silu (all f16x2) ----
    {
        float4 wc0 = *(const float4*)(smf + SB_W1C / 4 + lane * 4);
        float4 wc1 = *(const float4*)(smf + SB_W1C / 4 + lane * 4 + 128);
        u32 wch[4];
        wch[0] = hpack2(wc0.x, wc0.y);
        wch[1] = hpack2(wc0.z, wc0.w);
        wch[2] = hpack2(wc1.x, wc1.y);
        wch[3] = hpack2(wc1.z, wc1.w);
#pragma unroll
        for (int i = 0; i < 8; i++) {
            int el = warp * 8 + i;
            const u32* ya = &g_yah[(size_t)rows[el] * 128];
            const u32* yb = &g_ybh[(size_t)cols[el] * 128];
            u32 de2 = hpack2(smf[SB_DE / 4 + el], smf[SB_DE / 4 + el]);
#pragma unroll
            for (int j = 0; j < 2; j++) {
                int yo = lane * 2 + j * 64;
                uint2 pa = *(const uint2*)(ya + yo);
                uint2 pb = *(const uint2*)(yb + yo);
                u32 s0 = hfma2_(de2, wch[j * 2], hadd2_(pa.x, pb.x));
                u32 s1 = hfma2_(de2, wch[j * 2 + 1], hadd2_(pa.y, pb.y));
                s0 = silu_h2(s0);
                s1 = silu_h2(s1);
                *(u64*)(smc + SB_A + el * ASTR + (lane * 4 + j * 128) * 2) =
                    (u64)s0 | ((u64)s1 << 32);
            }
        }
    }
    __syncthreads();

    // ---- GEMM2 (fp16): D2[64e x 128o], warp slice 32e x 32o, K=256 ----
    float acc2[2][4][4] = {};
#pragma unroll
    for (int ks = 0; ks < 16; ks++) {
        int ka = ks * 16;
        u32 ah[2][4];
        ldmA<ASTR>(ah[0], smb + SB_A, Eb, ka);
        ldmA<ASTR>(ah[1], smb + SB_A, Eb + 16, ka);
        int fbase = ((og * 16 + ks) * 2) * 32 + lane;
#pragma unroll
        for (int nq = 0; nq < 2; nq++) {
            uint4 f = g_fh2[fbase + nq * 32];
#pragma unroll
            for (int mt = 0; mt < 2; mt++) {
                mmaf16(acc2[mt][nq * 2], ah[mt], f.x, f.y);
                mmaf16(acc2[mt][nq * 2 + 1], ah[mt], f.z, f.w);
            }
        }
    }

    // ---- epilogue2: att partials (silu_f), cross-og combine ----
    {
        int r0 = lane >> 2, cb = (lane & 3) * 2;
        float p[2][2] = {};
#pragma unroll
        for (int mt = 0; mt < 2; mt++)
#pragma unroll
            for (int nb = 0; nb < 4; nb++) {
                int o = og * 32 + nb * 8 + cb;
                float b2a = smf[SB_B2 / 4 + o], b2b = smf[SB_B2 / 4 + o + 1];
                float w3a = smf[SB_W3 / 4 + o], w3b = smf[SB_W3 / 4 + o + 1];
                p[mt][0] += silu_f(acc2[mt][nb][0] + b2a) * w3a + silu_f(acc2[mt][nb][1] + b2b) * w3b;
                p[mt][1] += silu_f(acc2[mt][nb][2] + b2a) * w3a + silu_f(acc2[mt][nb][3] + b2b) * w3b;
            }
#pragma unroll
        for (int off = 1; off <= 2; off <<= 1)
#pragma unroll
            for (int mt = 0; mt < 2; mt++) {
                p[mt][0] += __shfl_xor_sync(0xffffffffu, p[mt][0], off);
                p[mt][1] += __shfl_xor_sync(0xffffffffu, p[mt][1], off);
            }
        if ((lane & 3) == 0) {
#pragma unroll
            for (int mt = 0; mt < 2; mt++) {
                int e = Eb + mt * 16 + r0;
                smf[SB_PART / 4 + og * 64 + e] = p[mt][0];
                smf[SB_PART / 4 + og * 64 + e + 8] = p[mt][1];
            }
        }
    }
    __syncthreads();
    if (tid < 64) {
        float z = smf[SB_PART / 4 + tid] + smf[SB_PART / 4 + 64 + tid] +
                  smf[SB_PART / 4 + 128 + tid] + smf[SB_PART / 4 + 192 + tid] + b3[0];
        smf[SB_ATT / 4 + tid] = sigm(z) * smf[SB_EMS / 4 + tid];  // accurate sigmoid
    }
    __syncthreads();

    // ---- scatter: g_out[row] += x_col * att  (fp32 x, accurate path) ----
#pragma unroll
    for (int i = 0; i < 8; i++) {
        int el = warp * 8 + i;
        float a = smf[SB_ATT / 4 + el];
        const float4 v = *(const float4*)&g_x[(size_t)cols[el] * DN + lane * 4];
        float* dst = &g_out[(size_t)rows[el] * DN + lane * 4];
        asm volatile("red.global.add.v4.f32 [%0], {%1, %2, %3, %4};"
                     :: "l"(dst), "f"(v.x * a), "f"(v.y * a), "f"(v.z * a), "f"(v.w * a)
                     : "memory");
    }
}

// ---------------------------------------------------------------------------
// k_node (mma, split-bf16 — output path): node_mlp + residual + LN + silu.
// ---------------------------------------------------------------------------
__global__ __launch_bounds__(256, 3) void k_node(
    const float* __restrict__ b1, const float* __restrict__ g1,
    const float* __restrict__ bb1, const float* __restrict__ b2,
    const float* __restrict__ g2, const float* __restrict__ bb2,
    float* __restrict__ out) {
    extern __shared__ char smc[];
    u32 smb = smem_u32(smc);
    float* mid = (float*)(smc + SN_MID);
    float* b1s = (float*)(smc + SN_B1);
    float* b2s = (float*)(smc + SN_B2);
    float* g1s = (float*)(smc + SN_G1);
    float* bb1s = (float*)(smc + SN_BB1);
    float* g2s = (float*)(smc + SN_G2);
    float* bb2s = (float*)(smc + SN_BB2);
    int tid = threadIdx.x, lane = tid & 31, warp = tid >> 5;
    int n0 = blockIdx.x * 32;

    if (tid < 128) {
        b1s[tid] = b1[tid]; b2s[tid] = b2[tid];
        g1s[tid] = g1[tid]; bb1s[tid] = bb1[tid];
        g2s[tid] = g2[tid]; bb2s[tid] = bb2[tid];
    }
#pragma unroll
    for (int i = 0; i < 4; i++) {
        int el = warp * 4 + i;
        float4 v = *(const float4*)&g_out[(size_t)(n0 + el) * DN + lane * 4];
        v.x *= 0.01f; v.y *= 0.01f; v.z *= 0.01f; v.w *= 0.01f;
        u32 hp0, lp0, hp1, lp1;
        bsplit2(v.x, v.y, hp0, lp0);
        bsplit2(v.z, v.w, hp1, lp1);
        *(u64*)(smc + SN_A_HI + el * YSTR + lane * 8) = (u64)hp0 | ((u64)hp1 << 32);
        *(u64*)(smc + SN_A_LO + el * YSTR + lane * 8) = (u64)lp0 | ((u64)lp1 << 32);
    }
    __syncthreads();

    int r0 = lane >> 2, cb = (lane & 3) * 2;

    // ---- GEMM1 (nm_w1) ----
    {
        float acc[2][2][4] = {};
#pragma unroll
        for (int ks = 0; ks < 8; ks++) {
            int ka = ks * 16;
            u32 ah[2][4], al_[2][4];
            ldmA<YSTR>(ah[0], smb + SN_A_HI, 0, ka);
            ldmA<YSTR>(ah[1], smb + SN_A_HI, 16, ka);
            ldmA<YSTR>(al_[0], smb + SN_A_LO, 0, ka);
            ldmA<YSTR>(al_[1], smb + SN_A_LO, 16, ka);
            int fbase = ((warp * 8 + ks) * 32 + lane) * 2;
            uint4 fh = g_fn1[fbase];
            uint4 fl = g_fn1[fbase + 1];
#pragma unroll
            for (int mt = 0; mt < 2; mt++) {
                mma16816(acc[mt][0], ah[mt], fh.x, fh.y);
                mma16816(acc[mt][0], ah[mt], fl.x, fl.y);
                mma16816(acc[mt][0], al_[mt], fh.x, fh.y);
                mma16816(acc[mt][1], ah[mt], fh.z, fh.w);
                mma16816(acc[mt][1], ah[mt], fl.z, fl.w);
                mma16816(acc[mt][1], al_[mt], fh.z, fh.w);
            }
        }
#pragma unroll
        for (int mt = 0; mt < 2; mt++)
#pragma unroll
            for (int nb = 0; nb < 2; nb++) {
                int o = warp * 16 + nb * 8 + cb;
                float ba = b1s[o], bb = b1s[o + 1];
                int nl = mt * 16 + r0;
                *(float2*)&mid[nl * 132 + o] = make_float2(acc[mt][nb][0] + ba, acc[mt][nb][1] + bb);
                *(float2*)&mid[(nl + 8) * 132 + o] = make_float2(acc[mt][nb][2] + ba, acc[mt][nb][3] + bb);
            }
    }
    __syncthreads();

    // ---- LN1 + silu_f -> A ----
#pragma unroll
    for (int i = 0; i < 4; i++) {
        int nl = warp * 4 + i;
        float v[4], s1 = 0.f, s2 = 0.f;
#pragma unroll
        for (int j = 0; j < 4; j++) {
            v[j] = mid[nl * 132 + lane + 32 * j];
            s1 += v[j]; s2 += v[j] * v[j];
        }
#pragma unroll
        for (int off = 16; off > 0; off >>= 1) {
            s1 += __shfl_xor_sync(0xffffffffu, s1, off);
            s2 += __shfl_xor_sync(0xffffffffu, s2, off);
        }
        float mean = s1 * (1.0f / 128.0f);
        float var = s2 * (1.0f / 128.0f) - mean * mean;
        float inv = rsqrtf(var + 1e-5f);
#pragma unroll
        for (int j = 0; j < 4; j++) {
            int o = lane + 32 * j;
            float y = silu_f((v[j] - mean) * inv * g1s[o] + bb1s[o]);
            u16 hh, ll;
            bsplit(y, hh, ll);
            *(u16*)(smc + SN_A_HI + nl * YSTR + o * 2) = hh;
            *(u16*)(smc + SN_A_LO + nl * YSTR + o * 2) = ll;
        }
    }
    __syncthreads();

    // ---- GEMM2 (nm_w2) ----
    {
        float acc[2][2][4] = {};
#pragma unroll
        for (int ks = 0; ks < 8; ks++) {
            int ka = ks * 16;
            u32 ah[2][4], al_[2][4];
            ldmA<YSTR>(ah[0], smb + SN_A_HI, 0, ka);
            ldmA<YSTR>(ah[1], smb + SN_A_HI, 16, ka);
            ldmA<YSTR>(al_[0], smb + SN_A_LO, 0, ka);
            ldmA<YSTR>(al_[1], smb + SN_A_LO, 16, ka);
            int fbase = ((warp * 8 + ks) * 32 + lane) * 2;
            uint4 fh = g_fn2[fbase];
            uint4 fl = g_fn2[fbase + 1];
#pragma unroll
            for (int mt = 0; mt < 2; mt++) {
                mma16816(acc[mt][0], ah[mt], fh.x, fh.y);
                mma16816(acc[mt][0], ah[mt], fl.x, fl.y);
                mma16816(acc[mt][0], al_[mt], fh.x, fh.y);
                mma16816(acc[mt][1], ah[mt], fh.z, fh.w);
                mma16816(acc[mt][1], ah[mt], fl.z, fl.w);
                mma16816(acc[mt][1], al_[mt], fh.z, fh.w);
            }
        }
#pragma unroll
        for (int mt = 0; mt < 2; mt++)
#pragma unroll
            for (int nb = 0; nb < 2; nb++) {
                int o = warp * 16 + nb * 8 + cb;
                float ba = b2s[o], bb = b2s[o + 1];
                int nl = mt * 16 + r0;
                *(float2*)&mid[nl * 132 + o] = make_float2(acc[mt][nb][0] + ba, acc[mt][nb][1] + bb);
                *(float2*)&mid[(nl + 8) * 132 + o] = make_float2(acc[mt][nb][2] + ba, acc[mt][nb][3] + bb);
            }
    }
    __syncthreads();

    // ---- + residual, LN2, silu (accurate), store ----
#pragma unroll
    for (int i = 0; i < 4; i++) {
        int nl = warp * 4 + i;
        float v[4], s1 = 0.f, s2 = 0.f;
#pragma unroll
        for (int j = 0; j < 4; j++) {
            int o = lane + 32 * j;
            v[j] = mid[nl * 132 + o] + g_x[(size_t)(n0 + nl) * DN + o];
            s1 += v[j]; s2 += v[j] * v[j];
        }
#pragma unroll
        for (int off = 16; off > 0; off >>= 1) {
            s1 += __shfl_xor_sync(0xffffffffu, s1, off);
            s2 += __shfl_xor_sync(0xffffffffu, s2, off);
        }
        float mean = s1 * (1.0f / 128.0f);
        float var = s2 * (1.0f / 128.0f) - mean * mean;
        float inv = rsqrtf(var + 1e-5f);
#pragma unroll
        for (int j = 0; j < 4; j++) {
            int o = lane + 32 * j;
            float y = (v[j] - mean) * inv * g2s[o] + bb2s[o];
            out[(size_t)(n0 + nl) * DN + o] = silu_(y);
        }
    }
}

// ---------------------------------------------------------------------------
extern "C" void kernel_launch(void* const* d_in, const int* in_sizes, int n_in,
                              void* d_out, int out_size) {
    const float* h = (const float*)d_in[0];
    const float* distances = (const float*)d_in[1];
    const float* edge_mask = (const float*)d_in[3];
    const float* lin_w = (const float*)d_in[4];
    const float* lin_b = (const float*)d_in[5];
    const float* att_w1 = (const float*)d_in[6];
    const float* att_b1 = (const float*)d_in[7];
    const float* att_w2 = (const float*)d_in[8];
    const float* att_b2 = (const float*)d_in[9];
    const float* att_w3 = (const float*)d_in[10];
    const float* att_b3 = (const float*)d_in[11];
    const float* nm_w1 = (const float*)d_in[12];
    const float* nm_b1 = (const float*)d_in[13];
    const float* nm_ln_g = (const float*)d_in[14];
    const float* nm_ln_b = (const float*)d_in[15];
    const float* nm_w2 = (const float*)d_in[16];
    const float* nm_b2 = (const float*)d_in[17];
    const float* ln_g = (const float*)d_in[18];
    const float* ln_b = (const float*)d_in[19];
    const void* edges = d_in[20];

    cudaFuncSetAttribute(k_xy, cudaFuncAttributeMaxDynamicSharedMemorySize, SMEM_Y);
    cudaFuncSetAttribute(k_edge, cudaFuncAttributeMaxDynamicSharedMemorySize, SMEM_EDGE);
    cudaFuncSetAttribute(k_node, cudaFuncAttributeMaxDynamicSharedMemorySize, SMEM_N);

    k_prep<<<72, 256>>>(att_w1, att_w2, lin_w, nm_w1, nm_w2, edges);
    k_xy<<<625, 256, SMEM_Y>>>(h, lin_b, att_b1);
    k_edge<<<NCTA, 256, SMEM_EDGE>>>(distances, edge_mask, att_w1, att_b2,
                                     att_w3, att_b3, edges);
    k_node<<<625, 256, SMEM_N>>>(nm_b1, nm_ln_g, nm_ln_b,
                                 nm_b2, ln_g, ln_b, (float*)d_out);
}

// round 17
// speedup vs baseline: 1.0553x; 1.0296x over previous
#include <cuda_runtime.h>
#include <cuda_bf16.h>
#include <cuda_fp16.h>

typedef unsigned int u32;
typedef unsigned long long u64;
typedef unsigned short u16;

#define DN 128
#define NN 20000
#define EE 640000
#define ET 32                   // edges per CTA (128 threads)
#define NCTA (EE / ET)          // 20000
#define ASTR 528                // h1 row stride bytes (256 halves + pad)
#define YSTR 272                // x row stride bytes (136 halves)

// ---------------- device globals (no runtime alloc) ----------------
__device__ float g_x[NN * DN];
__device__ float g_out[NN * DN];
__device__ u32 g_yah[NN * 128];    // (x@W1a^T + b1) as fp16 pairs
__device__ u32 g_ybh[NN * 128];    // (x@W1b^T) as fp16 pairs
__device__ int g_e64;
// pre-packed B fragments in per-lane mma order
__device__ uint4 g_fh1[8192];   // W1 fp16 single: [og4][side2][ks8][nq4][lane32]
__device__ uint4 g_fh2[4096];   // W2 fp16 single: [og4][ks16][nq2][lane32]
__device__ uint4 g_fl[4096];    // lin_w bf16 hi/lo: [og8][ks8][lane32][hi/lo]
__device__ uint4 g_fn1[4096];   // nm_w1 bf16 hi/lo
__device__ uint4 g_fn2[4096];   // nm_w2 bf16 hi/lo

// ---------------- k_edge smem layout (bytes), ET=32 ----------------
#define SB_ROWS 0               // 32 int
#define SB_COLS 128
#define SB_DE   256
#define SB_EMS  384
#define SB_ATT  512
#define SB_PART 640             // 4 og x 32 = 128 f
#define SB_B2   1152            // 128 f
#define SB_W3   1664            // 128 f
#define SB_W1C  2176            // 256 f
#define SB_A    3200            // 32 x 528 = 16896 (fp16 h1 tile)
#define SMEM_EDGE 20096

// ---------------- k_xy smem layout ----------------
#define SY_A_HI 0               // 32 x 272 = 8704
#define SY_A_LO 8704
#define SY_B1   17408           // 256 f
#define SY_LB   18432           // 128 f
#define SMEM_Y  18944

// ---------------- k_node smem layout ----------------
#define SN_A_HI 0               // 32 x 272 = 8704
#define SN_A_LO 8704
#define SN_MID  17408           // 32 x 132 f = 16896
#define SN_B1   34304           // 128 f
#define SN_B2   34816
#define SN_G1   35328
#define SN_BB1  35840
#define SN_G2   36352
#define SN_BB2  36864
#define SMEM_N  37376

__device__ __forceinline__ u32 smem_u32(const void* p) {
    u32 a;
    asm("{ .reg .u64 t; cvta.to.shared.u64 t, %1; cvt.u32.u64 %0, t; }" : "=r"(a) : "l"(p));
    return a;
}
// accurate sigmoid (output path)
__device__ __forceinline__ float sigm(float v) {
    return __fdividef(1.0f, 1.0f + __expf(-v));
}
__device__ __forceinline__ float silu_(float v) { return v * sigm(v); }
// fast fp32 sigmoid (attenuated scalar paths)
__device__ __forceinline__ float tanhap(float x) {
    float r; asm("tanh.approx.f32 %0, %1;" : "=f"(r) : "f"(x)); return r;
}
__device__ __forceinline__ float sigm_f(float v) { return fmaf(tanhap(v * 0.5f), 0.5f, 0.5f); }
__device__ __forceinline__ float silu_f(float v) { return v * sigm_f(v); }

// half2 helpers (attenuated h1 path)
__device__ __forceinline__ u32 hadd2_(u32 a, u32 b) {
    u32 r; asm("add.rn.f16x2 %0, %1, %2;" : "=r"(r) : "r"(a), "r"(b)); return r;
}
__device__ __forceinline__ u32 hfma2_(u32 a, u32 b, u32 c) {
    u32 r; asm("fma.rn.f16x2 %0, %1, %2, %3;" : "=r"(r) : "r"(a), "r"(b), "r"(c)); return r;
}
__device__ __forceinline__ u32 silu_h2(u32 v) {
    const u32 h05 = 0x38003800u;   // half2(0.5, 0.5)
    u32 t, s;
    asm("mul.rn.f16x2 %0, %1, %2;" : "=r"(t) : "r"(v), "r"(h05));
    asm("tanh.approx.f16x2 %0, %1;" : "=r"(t) : "r"(t));
    asm("fma.rn.f16x2 %0, %1, %2, %3;" : "=r"(s) : "r"(t), "r"(h05), "r"(h05));
    asm("mul.rn.f16x2 %0, %1, %2;" : "=r"(s) : "r"(s), "r"(v));
    return s;
}

__device__ __forceinline__ void bsplit(float v, u16& h, u16& l) {
    __nv_bfloat16 hb = __float2bfloat16(v);
    __nv_bfloat16 lb = __float2bfloat16(v - __bfloat162float(hb));
    h = __bfloat16_as_ushort(hb);
    l = __bfloat16_as_ushort(lb);
}
__device__ __forceinline__ void bsplit2(float v0, float v1, u32& hp, u32& lp) {
    asm("cvt.rn.bf16x2.f32 %0, %1, %2;" : "=r"(hp) : "f"(v1), "f"(v0));
    float h0 = __uint_as_float(hp << 16);
    float h1 = __uint_as_float(hp & 0xffff0000u);
    asm("cvt.rn.bf16x2.f32 %0, %1, %2;" : "=r"(lp) : "f"(v1 - h1), "f"(v0 - h0));
}
__device__ __forceinline__ u32 hpack2(float v0, float v1) {
    u32 r;
    asm("cvt.rn.f16x2.f32 %0, %1, %2;" : "=r"(r) : "f"(v1), "f"(v0));
    return r;
}

// ldmatrix m16k16 (A, row-major, stride S bytes)
template <int S>
__device__ __forceinline__ void ldmA(u32 r[4], u32 base, int row0, int kh) {
    int lane = threadIdx.x & 31;
    int quad = lane >> 3;
    u32 addr = base + (u32)(row0 + (lane & 7) + (quad & 1) * 8) * S +
               (u32)kh * 2 + (u32)(quad >> 1) * 16;
    asm volatile("ldmatrix.sync.aligned.m8n8.x4.shared.b16 {%0,%1,%2,%3}, [%4];"
                 : "=r"(r[0]), "=r"(r[1]), "=r"(r[2]), "=r"(r[3]) : "r"(addr));
}
__device__ __forceinline__ void mma16816(float d[4], const u32 a[4], u32 b0, u32 b1) {
    asm volatile("mma.sync.aligned.m16n8k16.row.col.f32.bf16.bf16.f32 "
                 "{%0,%1,%2,%3}, {%4,%5,%6,%7}, {%8,%9}, {%0,%1,%2,%3};"
                 : "+f"(d[0]), "+f"(d[1]), "+f"(d[2]), "+f"(d[3])
                 : "r"(a[0]), "r"(a[1]), "r"(a[2]), "r"(a[3]), "r"(b0), "r"(b1));
}
__device__ __forceinline__ void mmaf16(float d[4], const u32 a[4], u32 b0, u32 b1) {
    asm volatile("mma.sync.aligned.m16n8k16.row.col.f32.f16.f16.f32 "
                 "{%0,%1,%2,%3}, {%4,%5,%6,%7}, {%8,%9}, {%0,%1,%2,%3};"
                 : "+f"(d[0]), "+f"(d[1]), "+f"(d[2]), "+f"(d[3])
                 : "r"(a[0]), "r"(a[1]), "r"(a[2]), "r"(a[3]), "r"(b0), "r"(b1));
}

// pack a 128x128 K-major fp32 weight into bf16 hi/lo frag pairs
__device__ __forceinline__ void pack128(const float* __restrict__ w, uint4* tab, int j) {
    int lane = j & 31, ks = (j >> 5) & 7, og = (j >> 8) & 7;
    int nb0 = og * 16 + (lane >> 2);
    int kb = ks * 16 + (lane & 3) * 2;
    u32 wh[4], wl[4];
#pragma unroll
    for (int nb = 0; nb < 2; nb++)
#pragma unroll
        for (int r = 0; r < 2; r++) {
            const float* p = &w[(nb0 + nb * 8) * 128 + kb + r * 8];
            u16 h0, l0, h1, l1;
            bsplit(p[0], h0, l0);
            bsplit(p[1], h1, l1);
            wh[nb * 2 + r] = (u32)h0 | ((u32)h1 << 16);
            wl[nb * 2 + r] = (u32)l0 | ((u32)l1 << 16);
        }
    tab[j * 2] = make_uint4(wh[0], wh[1], wh[2], wh[3]);
    tab[j * 2 + 1] = make_uint4(wl[0], wl[1], wl[2], wl[3]);
}

// ---------------------------------------------------------------------------
// k_prep: pack weight fragment tables. grid 72 x 256.
// ---------------------------------------------------------------------------
__global__ void k_prep(const float* __restrict__ w1, const float* __restrict__ w2,
                       const float* __restrict__ lw, const float* __restrict__ nw1,
                       const float* __restrict__ nw2, const void* __restrict__ edges) {
    int idx = blockIdx.x * 256 + threadIdx.x;
    if (idx < 8192) {       // W1 fp16 single frags [256 out][257 k]
        int lane = idx & 31, nq = (idx >> 5) & 3, ks = (idx >> 7) & 7;
        int side = (idx >> 10) & 1, og = (idx >> 11) & 3;
        int nb0 = og * 64 + nq * 16 + (lane >> 2);
        int kb = side * 128 + ks * 16 + (lane & 3) * 2;
        u32 wf[4];
#pragma unroll
        for (int nb = 0; nb < 2; nb++)
#pragma unroll
            for (int r = 0; r < 2; r++) {
                const float* p = &w1[(nb0 + nb * 8) * 257 + kb + r * 8];
                wf[nb * 2 + r] = hpack2(p[0], p[1]);
            }
        g_fh1[idx] = make_uint4(wf[0], wf[1], wf[2], wf[3]);
    } else if (idx < 12288) {  // W2 fp16 single frags [128 out][256 k]
        int j = idx - 8192;
        int lane = j & 31, nq = (j >> 5) & 1, ks = (j >> 6) & 15, og = (j >> 10) & 3;
        int nb0 = og * 32 + nq * 16 + (lane >> 2);
        int kb = ks * 16 + (lane & 3) * 2;
        u32 wf[4];
#pragma unroll
        for (int nb = 0; nb < 2; nb++)
#pragma unroll
            for (int r = 0; r < 2; r++) {
                const float* p = &w2[(nb0 + nb * 8) * 256 + kb + r * 8];
                wf[nb * 2 + r] = hpack2(p[0], p[1]);
            }
        g_fh2[j] = make_uint4(wf[0], wf[1], wf[2], wf[3]);
    } else if (idx < 14336) {  // lin_w frags
        pack128(lw, g_fl, idx - 12288);
    } else if (idx < 16384) {  // nm_w1 frags
        pack128(nw1, g_fn1, idx - 14336);
    } else {                   // nm_w2 frags
        pack128(nw2, g_fn2, idx - 16384);
    }
    if (idx == 0) {
        const int* e32 = (const int*)edges;
        int nz = 0;
        for (int i = 0; i < 16; i++) nz |= e32[2 * i + 1];
        g_e64 = (nz == 0) ? 1 : 0;
    }
}

// ---------------------------------------------------------------------------
// k_xy: zero g_out rows; phase1 x = h@lin_w^T + lin_b (bf16 split);
//       phase2 ya/yb = x@W1^T (single fp16).  32 nodes/CTA, 2 CTAs/SM.
// ---------------------------------------------------------------------------
__global__ __launch_bounds__(256, 2) void k_xy(const float* __restrict__ h,
                                               const float* __restrict__ lb,
                                               const float* __restrict__ b1) {
    extern __shared__ char smc[];
    u32 smb = smem_u32(smc);
    float* b1s = (float*)(smc + SY_B1);
    float* lbs = (float*)(smc + SY_LB);
    int tid = threadIdx.x, lane = tid & 31, warp = tid >> 5;
    int n0 = blockIdx.x * 32;

    // zero this CTA's g_out rows (replaces k_zero launch)
#pragma unroll
    for (int i = 0; i < 4; i++) {
        int idx = tid + i * 256;
        *(float4*)&g_out[(size_t)n0 * DN + idx * 4] = make_float4(0.f, 0.f, 0.f, 0.f);
    }

    b1s[tid] = b1[tid];
    if (tid < 128) lbs[tid] = lb[tid];
#pragma unroll
    for (int i = 0; i < 4; i++) {
        int el = warp * 4 + i;
        const float4 v = *(const float4*)&h[(size_t)(n0 + el) * DN + lane * 4];
        u32 hp0, lp0, hp1, lp1;
        bsplit2(v.x, v.y, hp0, lp0);
        bsplit2(v.z, v.w, hp1, lp1);
        *(u64*)(smc + SY_A_HI + el * YSTR + lane * 8) = (u64)hp0 | ((u64)hp1 << 32);
        *(u64*)(smc + SY_A_LO + el * YSTR + lane * 8) = (u64)lp0 | ((u64)lp1 << 32);
    }
    __syncthreads();

    // ---- phase 1: x = h@lin_w^T + lin_b (bf16 hi/lo split) ----
    {
        float accl[2][2][4] = {};
#pragma unroll
        for (int ks = 0; ks < 8; ks++) {
            int ka = ks * 16;
            u32 ah[2][4], al_[2][4];
            ldmA<YSTR>(ah[0], smb + SY_A_HI, 0, ka);
            ldmA<YSTR>(ah[1], smb + SY_A_HI, 16, ka);
            ldmA<YSTR>(al_[0], smb + SY_A_LO, 0, ka);
            ldmA<YSTR>(al_[1], smb + SY_A_LO, 16, ka);
            int fbase = ((warp * 8 + ks) * 32 + lane) * 2;
            uint4 fh = g_fl[fbase];
            uint4 fl = g_fl[fbase + 1];
#pragma unroll
            for (int mt = 0; mt < 2; mt++) {
                mma16816(accl[mt][0], ah[mt], fh.x, fh.y);
                mma16816(accl[mt][0], ah[mt], fl.x, fl.y);
                mma16816(accl[mt][0], al_[mt], fh.x, fh.y);
                mma16816(accl[mt][1], ah[mt], fh.z, fh.w);
                mma16816(accl[mt][1], ah[mt], fl.z, fl.w);
                mma16816(accl[mt][1], al_[mt], fh.z, fh.w);
            }
        }
        __syncthreads();   // done reading h tile; overlay fp16 x tile
        int r0 = lane >> 2, cb = (lane & 3) * 2;
#pragma unroll
        for (int mt = 0; mt < 2; mt++) {
#pragma unroll
            for (int nb = 0; nb < 2; nb++) {
                int o = warp * 16 + nb * 8 + cb;
                float ba = lbs[o], bb = lbs[o + 1];
                float v0 = accl[mt][nb][0] + ba, v1 = accl[mt][nb][1] + bb;
                float v2 = accl[mt][nb][2] + ba, v3 = accl[mt][nb][3] + bb;
                int nl = mt * 16 + r0;
                *(float2*)&g_x[(size_t)(n0 + nl) * DN + o] = make_float2(v0, v1);
                *(float2*)&g_x[(size_t)(n0 + nl + 8) * DN + o] = make_float2(v2, v3);
                *(u32*)(smc + SY_A_HI + nl * YSTR + o * 2) = hpack2(v0, v1);
                *(u32*)(smc + SY_A_HI + (nl + 8) * YSTR + o * 2) = hpack2(v2, v3);
            }
        }
    }
    __syncthreads();

    // ---- phase 2: ya/yb single fp16 mma ----
    int side = warp >> 2, og1 = warp & 3;
    int r0 = lane >> 2, cb = (lane & 3) * 2;
    u32* dsth = side == 0 ? g_yah : g_ybh;
    float acc[2][8][4] = {};
#pragma unroll
    for (int ks = 0; ks < 8; ks++) {
        int ka = ks * 16;
        u32 ah[2][4];
        ldmA<YSTR>(ah[0], smb + SY_A_HI, 0, ka);
        ldmA<YSTR>(ah[1], smb + SY_A_HI, 16, ka);
        int fbase = (((og1 * 2 + side) * 8 + ks) * 4) * 32 + lane;
#pragma unroll
        for (int nq = 0; nq < 4; nq++) {
            uint4 f = g_fh1[fbase + nq * 32];
#pragma unroll
            for (int mt = 0; mt < 2; mt++) {
                mmaf16(acc[mt][nq * 2], ah[mt], f.x, f.y);
                mmaf16(acc[mt][nq * 2 + 1], ah[mt], f.z, f.w);
            }
        }
    }
#pragma unroll
    for (int mt = 0; mt < 2; mt++) {
        int node = n0 + mt * 16 + r0;
#pragma unroll
        for (int nb = 0; nb < 8; nb++) {
            int o = og1 * 64 + nb * 8 + cb;
            float ba = side == 0 ? b1s[o] : 0.0f;
            float bb = side == 0 ? b1s[o + 1] : 0.0f;
            dsth[(size_t)node * 128 + (o >> 1)] =
                hpack2(acc[mt][nb][0] + ba, acc[mt][nb][1] + bb);
            dsth[(size_t)(node + 8) * 128 + (o >> 1)] =
                hpack2(acc[mt][nb][2] + ba, acc[mt][nb][3] + bb);
        }
    }
}

// ---------------------------------------------------------------------------
// Fused edge kernel: 128 threads, ET=32, 8 CTAs/SM.  4 warps = 4 out-groups,
// each warp covers all 32 edges x 32 outs.  Same numerics as R16.
// ---------------------------------------------------------------------------
__global__ __launch_bounds__(128, 8) void k_edge(
    const float* __restrict__ dist, const float* __restrict__ emask,
    const float* __restrict__ w1, const float* __restrict__ b2,
    const float* __restrict__ w3, const float* __restrict__ b3,
    const void* __restrict__ edges) {
    extern __shared__ char smc[];
    u32 smb = smem_u32(smc);
    float* smf = (float*)smc;
    int* rows = (int*)(smc + SB_ROWS);
    int* cols = (int*)(smc + SB_COLS);

    int tid = threadIdx.x, lane = tid & 31, warp = tid >> 5;
    int og = warp;                 // 4 out-groups, 1 edge-group
    int e0 = blockIdx.x * ET;

    // stage small vectors (128 threads)
    smf[SB_W1C / 4 + tid] = w1[tid * 257 + 256];
    smf[SB_W1C / 4 + 128 + tid] = w1[(tid + 128) * 257 + 256];
    smf[SB_B2 / 4 + tid] = b2[tid];
    smf[SB_W3 / 4 + tid] = w3[tid];
    if (tid < 32) {
        int e = e0 + tid;
        if (g_e64) {
            const long long* e64 = (const long long*)edges;
            rows[tid] = (int)e64[e];
            cols[tid] = (int)e64[EE + e];
        } else {
            const int* ei = (const int*)edges;
            rows[tid] = ei[e];
            cols[tid] = ei[EE + e];
        }
        float em = emask[e];
        smf[SB_EMS / 4 + tid] = em;
        smf[SB_DE / 4 + tid] = dist[e] * em;
    }
    __syncthreads();

    // ---- gather fp16 ya[row]+yb[col]+de*w1c -> silu (all f16x2) ----
    {
        float4 wc0 = *(const float4*)(smf + SB_W1C / 4 + lane * 4);
        float4 wc1 = *(const float4*)(smf + SB_W1C / 4 + lane * 4 + 128);
        u32 wch[4];
        wch[0] = hpack2(wc0.x, wc0.y);
        wch[1] = hpack2(wc0.z, wc0.w);
        wch[2] = hpack2(wc1.x, wc1.y);
        wch[3] = hpack2(wc1.z, wc1.w);
#pragma unroll
        for (int i = 0; i < 8; i++) {
            int el = warp * 8 + i;
            const u32* ya = &g_yah[(size_t)rows[el] * 128];
            const u32* yb = &g_ybh[(size_t)cols[el] * 128];
            u32 de2 = hpack2(smf[SB_DE / 4 + el], smf[SB_DE / 4 + el]);
#pragma unroll
            for (int j = 0; j < 2; j++) {
                int yo = lane * 2 + j * 64;
                uint2 pa = *(const uint2*)(ya + yo);
                uint2 pb = *(const uint2*)(yb + yo);
                u32 s0 = hfma2_(de2, wch[j * 2], hadd2_(pa.x, pb.x));
                u32 s1 = hfma2_(de2, wch[j * 2 + 1], hadd2_(pa.y, pb.y));
                s0 = silu_h2(s0);
                s1 = silu_h2(s1);
                *(u64*)(smc + SB_A + el * ASTR + (lane * 4 + j * 128) * 2) =
                    (u64)s0 | ((u64)s1 << 32);
            }
        }
    }
    __syncthreads();

    // ---- GEMM2 (fp16): D2[32e x 128o], warp slice 32e x 32o, K=256 ----
    float acc2[2][4][4] = {};
#pragma unroll
    for (int ks = 0; ks < 16; ks++) {
        int ka = ks * 16;
        u32 ah[2][4];
        ldmA<ASTR>(ah[0], smb + SB_A, 0, ka);
        ldmA<ASTR>(ah[1], smb + SB_A, 16, ka);
        int fbase = ((og * 16 + ks) * 2) * 32 + lane;
#pragma unroll
        for (int nq = 0; nq < 2; nq++) {
            uint4 f = g_fh2[fbase + nq * 32];
#pragma unroll
            for (int mt = 0; mt < 2; mt++) {
                mmaf16(acc2[mt][nq * 2], ah[mt], f.x, f.y);
                mmaf16(acc2[mt][nq * 2 + 1], ah[mt], f.z, f.w);
            }
        }
    }

    // ---- epilogue2: att partials (silu_f), cross-og combine ----
    {
        int r0 = lane >> 2, cb = (lane & 3) * 2;
        float p[2][2] = {};
#pragma unroll
        for (int mt = 0; mt < 2; mt++)
#pragma unroll
            for (int nb = 0; nb < 4; nb++) {
                int o = og * 32 + nb * 8 + cb;
                float b2a = smf[SB_B2 / 4 + o], b2b = smf[SB_B2 / 4 + o + 1];
                float w3a = smf[SB_W3 / 4 + o], w3b = smf[SB_W3 / 4 + o + 1];
                p[mt][0] += silu_f(acc2[mt][nb][0] + b2a) * w3a + silu_f(acc2[mt][nb][1] + b2b) * w3b;
                p[mt][1] += silu_f(acc2[mt][nb][2] + b2a) * w3a + silu_f(acc2[mt][nb][3] + b2b) * w3b;
            }
#pragma unroll
        for (int off = 1; off <= 2; off <<= 1)
#pragma unroll
            for (int mt = 0; mt < 2; mt++) {
                p[mt][0] += __shfl_xor_sync(0xffffffffu, p[mt][0], off);
                p[mt][1] += __shfl_xor_sync(0xffffffffu, p[mt][1], off);
            }
        if ((lane & 3) == 0) {
#pragma unroll
            for (int mt = 0; mt < 2; mt++) {
                int e = mt * 16 + r0;
                smf[SB_PART / 4 + og * 32 + e] = p[mt][0];
                smf[SB_PART / 4 + og * 32 + e + 8] = p[mt][1];
            }
        }
    }
    __syncthreads();
    if (tid < 32) {
        float z = smf[SB_PART / 4 + tid] + smf[SB_PART / 4 + 32 + tid] +
                  smf[SB_PART / 4 + 64 + tid] + smf[SB_PART / 4 + 96 + tid] + b3[0];
        smf[SB_ATT / 4 + tid] = sigm(z) * smf[SB_EMS / 4 + tid];  // accurate sigmoid
    }
    __syncthreads();

    // ---- scatter: g_out[row] += x_col * att  (fp32 x, accurate path) ----
#pragma unroll
    for (int i = 0; i < 8; i++) {
        int el = warp * 8 + i;
        float a = smf[SB_ATT / 4 + el];
        const float4 v = *(const float4*)&g_x[(size_t)cols[el] * DN + lane * 4];
        float* dst = &g_out[(size_t)rows[el] * DN + lane * 4];
        asm volatile("red.global.add.v4.f32 [%0], {%1, %2, %3, %4};"
                     :: "l"(dst), "f"(v.x * a), "f"(v.y * a), "f"(v.z * a), "f"(v.w * a)
                     : "memory");
    }
}

// ---------------------------------------------------------------------------
// k_node (mma, split-bf16 — output path): node_mlp + residual + LN + silu.
// ---------------------------------------------------------------------------
__global__ __launch_bounds__(256, 4) void k_node(
    const float* __restrict__ b1, const float* __restrict__ g1,
    const float* __restrict__ bb1, const float* __restrict__ b2,
    const float* __restrict__ g2, const float* __restrict__ bb2,
    float* __restrict__ out) {
    extern __shared__ char smc[];
    u32 smb = smem_u32(smc);
    float* mid = (float*)(smc + SN_MID);
    float* b1s = (float*)(smc + SN_B1);
    float* b2s = (float*)(smc + SN_B2);
    float* g1s = (float*)(smc + SN_G1);
    float* bb1s = (float*)(smc + SN_BB1);
    float* g2s = (float*)(smc + SN_G2);
    float* bb2s = (float*)(smc + SN_BB2);
    int tid = threadIdx.x, lane = tid & 31, warp = tid >> 5;
    int n0 = blockIdx.x * 32;

    if (tid < 128) {
        b1s[tid] = b1[tid]; b2s[tid] = b2[tid];
        g1s[tid] = g1[tid]; bb1s[tid] = bb1[tid];
        g2s[tid] = g2[tid]; bb2s[tid] = bb2[tid];
    }
#pragma unroll
    for (int i = 0; i < 4; i++) {
        int el = warp * 4 + i;
        float4 v = *(const float4*)&g_out[(size_t)(n0 + el) * DN + lane * 4];
        v.x *= 0.01f; v.y *= 0.01f; v.z *= 0.01f; v.w *= 0.01f;
        u32 hp0, lp0, hp1, lp1;
        bsplit2(v.x, v.y, hp0, lp0);
        bsplit2(v.z, v.w, hp1, lp1);
        *(u64*)(smc + SN_A_HI + el * YSTR + lane * 8) = (u64)hp0 | ((u64)hp1 << 32);
        *(u64*)(smc + SN_A_LO + el * YSTR + lane * 8) = (u64)lp0 | ((u64)lp1 << 32);
    }
    __syncthreads();

    int r0 = lane >> 2, cb = (lane & 3) * 2;

    // ---- GEMM1 (nm_w1) ----
    {
        float acc[2][2][4] = {};
#pragma unroll
        for (int ks = 0; ks < 8; ks++) {
            int ka = ks * 16;
            u32 ah[2][4], al_[2][4];
            ldmA<YSTR>(ah[0], smb + SN_A_HI, 0, ka);
            ldmA<YSTR>(ah[1], smb + SN_A_HI, 16, ka);
            ldmA<YSTR>(al_[0], smb + SN_A_LO, 0, ka);
            ldmA<YSTR>(al_[1], smb + SN_A_LO, 16, ka);
            int fbase = ((warp * 8 + ks) * 32 + lane) * 2;
            uint4 fh = g_fn1[fbase];
            uint4 fl = g_fn1[fbase + 1];
#pragma unroll
            for (int mt = 0; mt < 2; mt++) {
                mma16816(acc[mt][0], ah[mt], fh.x, fh.y);
                mma16816(acc[mt][0], ah[mt], fl.x, fl.y);
                mma16816(acc[mt][0], al_[mt], fh.x, fh.y);
                mma16816(acc[mt][1], ah[mt], fh.z, fh.w);
                mma16816(acc[mt][1], ah[mt], fl.z, fl.w);
                mma16816(acc[mt][1], al_[mt], fh.z, fh.w);
            }
        }
#pragma unroll
        for (int mt = 0; mt < 2; mt++)
#pragma unroll
            for (int nb = 0; nb < 2; nb++) {
                int o = warp * 16 + nb * 8 + cb;
                float ba = b1s[o], bb = b1s[o + 1];
                int nl = mt * 16 + r0;
                *(float2*)&mid[nl * 132 + o] = make_float2(acc[mt][nb][0] + ba, acc[mt][nb][1] + bb);
                *(float2*)&mid[(nl + 8) * 132 + o] = make_float2(acc[mt][nb][2] + ba, acc[mt][nb][3] + bb);
            }
    }
    __syncthreads();

    // ---- LN1 + silu_f -> A ----
#pragma unroll
    for (int i = 0; i < 4; i++) {
        int nl = warp * 4 + i;
        float v[4], s1 = 0.f, s2 = 0.f;
#pragma unroll
        for (int j = 0; j < 4; j++) {
            v[j] = mid[nl * 132 + lane + 32 * j];
            s1 += v[j]; s2 += v[j] * v[j];
        }
#pragma unroll
        for (int off = 16; off > 0; off >>= 1) {
            s1 += __shfl_xor_sync(0xffffffffu, s1, off);
            s2 += __shfl_xor_sync(0xffffffffu, s2, off);
        }
        float mean = s1 * (1.0f / 128.0f);
        float var = s2 * (1.0f / 128.0f) - mean * mean;
        float inv = rsqrtf(var + 1e-5f);
#pragma unroll
        for (int j = 0; j < 4; j++) {
            int o = lane + 32 * j;
            float y = silu_f((v[j] - mean) * inv * g1s[o] + bb1s[o]);
            u16 hh, ll;
            bsplit(y, hh, ll);
            *(u16*)(smc + SN_A_HI + nl * YSTR + o * 2) = hh;
            *(u16*)(smc + SN_A_LO + nl * YSTR + o * 2) = ll;
        }
    }
    __syncthreads();

    // ---- GEMM2 (nm_w2) ----
    {
        float acc[2][2][4] = {};
#pragma unroll
        for (int ks = 0; ks < 8; ks++) {
            int ka = ks * 16;
            u32 ah[2][4], al_[2][4];
            ldmA<YSTR>(ah[0], smb + SN_A_HI, 0, ka);
            ldmA<YSTR>(ah[1], smb + SN_A_HI, 16, ka);
            ldmA<YSTR>(al_[0], smb + SN_A_LO, 0, ka);
            ldmA<YSTR>(al_[1], smb + SN_A_LO, 16, ka);
            int fbase = ((warp * 8 + ks) * 32 + lane) * 2;
            uint4 fh = g_fn2[fbase];
            uint4 fl = g_fn2[fbase + 1];
#pragma unroll
            for (int mt = 0; mt < 2; mt++) {
                mma16816(acc[mt][0], ah[mt], fh.x, fh.y);
                mma16816(acc[mt][0], ah[mt], fl.x, fl.y);
                mma16816(acc[mt][0], al_[mt], fh.x, fh.y);
                mma16816(acc[mt][1], ah[mt], fh.z, fh.w);
                mma16816(acc[mt][1], ah[mt], fl.z, fl.w);
                mma16816(acc[mt][1], al_[mt], fh.z, fh.w);
            }
        }
#pragma unroll
        for (int mt = 0; mt < 2; mt++)
#pragma unroll
            for (int nb = 0; nb < 2; nb++) {
                int o = warp * 16 + nb * 8 + cb;
                float ba = b2s[o], bb = b2s[o + 1];
                int nl = mt * 16 + r0;
                *(float2*)&mid[nl * 132 + o] = make_float2(acc[mt][nb][0] + ba, acc[mt][nb][1] + bb);
                *(float2*)&mid[(nl + 8) * 132 + o] = make_float2(acc[mt][nb][2] + ba, acc[mt][nb][3] + bb);
            }
    }
    __syncthreads();

    // ---- + residual, LN2, silu (accurate), store ----
#pragma unroll
    for (int i = 0; i < 4; i++) {
        int nl = warp * 4 + i;
        float v[4], s1 = 0.f, s2 = 0.f;
#pragma unroll
        for (int j = 0; j < 4; j++) {
            int o = lane + 32 * j;
            v[j] = mid[nl * 132 + o] + g_x[(size_t)(n0 + nl) * DN + o];
            s1 += v[j]; s2 += v[j] * v[j];
        }
#pragma unroll
        for (int off = 16; off > 0; off >>= 1) {
            s1 += __shfl_xor_sync(0xffffffffu, s1, off);
            s2 += __shfl_xor_sync(0xffffffffu, s2, off);
        }
        float mean = s1 * (1.0f / 128.0f);
        float var = s2 * (1.0f / 128.0f) - mean * mean;
        float inv = rsqrtf(var + 1e-5f);
#pragma unroll
        for (int j = 0; j < 4; j++) {
            int o = lane + 32 * j;
            float y = (v[j] - mean) * inv * g2s[o] + bb2s[o];
            out[(size_t)(n0 + nl) * DN + o] = silu_(y);
        }
    }
}

// ---------------------------------------------------------------------------
extern "C" void kernel_launch(void* const* d_in, const int* in_sizes, int n_in,
                              void* d_out, int out_size) {
    const float* h = (const float*)d_in[0];
    const float* distances = (const float*)d_in[1];
    const float* edge_mask = (const float*)d_in[3];
    const float* lin_w = (const float*)d_in[4];
    const float* lin_b = (const float*)d_in[5];
    const float* att_w1 = (const float*)d_in[6];
    const float* att_b1 = (const float*)d_in[7];
    const float* att_w2 = (const float*)d_in[8];
    const float* att_b2 = (const float*)d_in[9];
    const float* att_w3 = (const float*)d_in[10];
    const float* att_b3 = (const float*)d_in[11];
    const float* nm_w1 = (const float*)d_in[12];
    const float* nm_b1 = (const float*)d_in[13];
    const float* nm_ln_g = (const float*)d_in[14];
    const float* nm_ln_b = (const float*)d_in[15];
    const float* nm_w2 = (const float*)d_in[16];
    const float* nm_b2 = (const float*)d_in[17];
    const float* ln_g = (const float*)d_in[18];
    const float* ln_b = (const float*)d_in[19];
    const void* edges = d_in[20];

    cudaFuncSetAttribute(k_xy, cudaFuncAttributeMaxDynamicSharedMemorySize, SMEM_Y);
    cudaFuncSetAttribute(k_edge, cudaFuncAttributeMaxDynamicSharedMemorySize, SMEM_EDGE);
    cudaFuncSetAttribute(k_node, cudaFuncAttributeMaxDynamicSharedMemorySize, SMEM_N);

    k_prep<<<72, 256>>>(att_w1, att_w2, lin_w, nm_w1, nm_w2, edges);
    k_xy<<<625, 256, SMEM_Y>>>(h, lin_b, att_b1);
    k_edge<<<NCTA, 128, SMEM_EDGE>>>(distances, edge_mask, att_w1, att_b2,
                                     att_w3, att_b3, edges);
    k_node<<<625, 256, SMEM_N>>>(nm_b1, nm_ln_g, nm_ln_b,
                                 nm_b2, ln_g, ln_b, (float*)d_out);
}